// round 12
// baseline (speedup 1.0000x reference)
#include <cuda_runtime.h>
#include <cuda_fp16.h>
#include <cstdint>
#include <math.h>

#define NODE   1280
#define PROJ   2560
#define ATTND  256
#define NREL   129
#define NL     4
#define BB     2
#define LL     1024
#define GVA_N  (2*PROJ + ATTND)   // 5376
#define ADALN_N (3*NODE)          // 3840
#define ROWS   (BB*LL)            // 2048
#define KS     10                 // adaLN split-K factor

// ---------------- scratch (device globals; no allocation allowed) ----------
__device__ float  d_sc    [BB*NODE];
__device__ float  d_part  [NL*BB*KS*ADALN_N];
__device__ float  d_gba   [NL*BB*ADALN_N];
__device__ __half d_x16   [ROWS*NODE];
__device__ __half d_h16   [ROWS*GVA_N];
__device__ __half d_q16   [ROWS*ATTND];
__device__ __half d_k16   [ROWS*ATTND];
__device__ float  d_attn  [(long)BB*LL*LL];
__device__ __half d_attn16[(long)BB*LL*LL];
__device__ __half d_av16  [ROWS*PROJ];
__device__ float  d_node  [ROWS*NODE];
__device__ __half d_wgva16[(long)NL*NODE*GVA_N];
__device__ __half d_wout16[(long)NL*PROJ*NODE];

// ---------------- helpers ---------------------------------------------------
__device__ __forceinline__ float siluf(float x) { return x / (1.f + __expf(-x)); }
__device__ __forceinline__ float warpMax(float v) {
    #pragma unroll
    for (int o = 16; o > 0; o >>= 1) v = fmaxf(v, __shfl_xor_sync(0xffffffffu, v, o));
    return v;
}
__device__ __forceinline__ float warpSum(float v) {
    #pragma unroll
    for (int o = 16; o > 0; o >>= 1) v += __shfl_xor_sync(0xffffffffu, v, o);
    return v;
}
__device__ __forceinline__ uint32_t smem_u32(const void* p) {
    uint32_t a;
    asm("{ .reg .u64 t; cvta.to.shared.u64 t, %1; cvt.u32.u64 %0, t; }"
        : "=r"(a) : "l"(p));
    return a;
}
__device__ __forceinline__ void cp16(uint32_t dst, const void* src) {
    asm volatile("cp.async.cg.shared.global [%0], [%1], 16;" :: "r"(dst), "l"(src));
}
__device__ __forceinline__ void cp_commit() {
    asm volatile("cp.async.commit_group;" ::: "memory");
}
template <int N>
__device__ __forceinline__ void cp_wait() {
    asm volatile("cp.async.wait_group %0;" :: "n"(N) : "memory");
}
__device__ __forceinline__ void ldm_x4(uint32_t* r, uint32_t a) {
    asm volatile("ldmatrix.sync.aligned.m8n8.x4.shared.b16 {%0,%1,%2,%3}, [%4];"
                 : "=r"(r[0]), "=r"(r[1]), "=r"(r[2]), "=r"(r[3]) : "r"(a));
}
__device__ __forceinline__ void ldm_x4_t(uint32_t* r, uint32_t a) {
    asm volatile("ldmatrix.sync.aligned.m8n8.x4.trans.shared.b16 {%0,%1,%2,%3}, [%4];"
                 : "=r"(r[0]), "=r"(r[1]), "=r"(r[2]), "=r"(r[3]) : "r"(a));
}
__device__ __forceinline__ void mma16816(float* c, const uint32_t* a, const uint32_t* b) {
    asm volatile(
        "mma.sync.aligned.m16n8k16.row.col.f32.f16.f16.f32 "
        "{%0,%1,%2,%3}, {%4,%5,%6,%7}, {%8,%9}, {%0,%1,%2,%3};"
        : "+f"(c[0]), "+f"(c[1]), "+f"(c[2]), "+f"(c[3])
        : "r"(a[0]), "r"(a[1]), "r"(a[2]), "r"(a[3]), "r"(b[0]), "r"(b[1]));
}

// ---------------- small kernels ---------------------------------------------
__global__ void silu_vec_k(const float* __restrict__ c, float* __restrict__ sc, int n) {
    int i = blockIdx.x * 256 + threadIdx.x;
    if (i < n) sc[i] = siluf(c[i]);
}

__global__ void f2h_k(const float* __restrict__ in, __half* __restrict__ out) {
    long i = (long)blockIdx.x * 256 + threadIdx.x;
    float4 v = ((const float4*)in)[i];
    ((__half2*)out)[2 * i]     = __floats2half2_rn(v.x, v.y);
    ((__half2*)out)[2 * i + 1] = __floats2half2_rn(v.z, v.w);
}

__global__ void adaln_part_k(const float* __restrict__ sc, const float* __restrict__ w,
                             float* __restrict__ part) {
    const int l = blockIdx.z;
    const int b = blockIdx.y / KS, ks = blockIdx.y % KS;
    const int col = blockIdx.x * 256 + threadIdx.x;
    const int KC = NODE / KS;                  // 128
    const float* s  = sc + b * NODE + ks * KC;
    const float* wp = w + (long)l * NODE * ADALN_N + (long)ks * KC * ADALN_N + col;
    float a0 = 0.f, a1 = 0.f;
    #pragma unroll 8
    for (int k = 0; k < KC; k += 2) {
        a0 = fmaf(s[k],     wp[(long)k * ADALN_N],       a0);
        a1 = fmaf(s[k + 1], wp[(long)(k + 1) * ADALN_N], a1);
    }
    part[((((long)l * BB) + b) * KS + ks) * ADALN_N + col] = a0 + a1;
}
__global__ void adaln_reduce_k(const float* __restrict__ part,
                               const float* __restrict__ bvec, float* __restrict__ gba) {
    long idx = (long)blockIdx.x * 256 + threadIdx.x;
    int l = (int)(idx / (BB * ADALN_N));
    int rem = (int)(idx % (BB * ADALN_N));
    int b = rem / ADALN_N, col = rem % ADALN_N;
    const float* p = part + (((long)l * BB + b) * KS) * ADALN_N + col;
    float acc = bvec[l * ADALN_N + col];
    #pragma unroll
    for (int i = 0; i < KS; i++) acc += p[(long)i * ADALN_N];
    gba[idx] = acc;
}

// LayerNorm + modulate -> fp16 x
__global__ __launch_bounds__(256) void ln_mod_k(const float* __restrict__ node,
                                                const float* __restrict__ gba,
                                                __half* __restrict__ x16) {
    const int row = blockIdx.x;
    const int b   = row >> 10;
    const float* p = node + (long)row * NODE;
    float vals[5];
    float s = 0.f, sq = 0.f;
    #pragma unroll
    for (int i = 0; i < 5; i++) {
        float v = p[threadIdx.x + i * 256];
        vals[i] = v; s += v; sq += v * v;
    }
    __shared__ float rs[8], rq[8];
    s = warpSum(s); sq = warpSum(sq);
    if ((threadIdx.x & 31) == 0) { rs[threadIdx.x >> 5] = s; rq[threadIdx.x >> 5] = sq; }
    __syncthreads();
    float ts = 0.f, tq = 0.f;
    #pragma unroll
    for (int i = 0; i < 8; i++) { ts += rs[i]; tq += rq[i]; }
    const float mean = ts * (1.f / NODE);
    const float var  = tq * (1.f / NODE) - mean * mean;
    const float rstd = rsqrtf(var + 1e-5f);
    const float* g = gba + (long)b * ADALN_N;
    __half* xo = x16 + (long)row * NODE;
    #pragma unroll
    for (int i = 0; i < 5; i++) {
        int c = threadIdx.x + i * 256;
        float v = (vals[i] - mean) * rstd;
        xo[c] = __float2half_rn(v * (1.f + g[c]) + g[NODE + c]);
    }
}

// ============================================================================
// fp16 mma.sync GEMM: CTA tile MTT x 128, 128 threads (4 warps, MTTx32 warp
// tile), BK=32, 3-stage cp.async pipeline, high occupancy.
// A: fp16 [M,K] row-major.
// B: BKM=false -> fp16 [K,N] row-major; SMEM [k][n], ldmatrix.trans (occ 5)
//    BKM=true  -> fp16 [N,K] row-major; SMEM [n][k], ldmatrix        (occ 4)
// MODE 1: CH = silu(acc + bias[n])                 (fp16 out)
// MODE 2: CH = acc * auxH[m,n]                     (fp16 out)
// MODE 3: C  = (acc + bias[n])*(1+alpha[n]) + auxF (fp32 out)
// MODE 4: C  = acc + bias[z,n] + rel[clamp(m-n)]   (fp32 out)
// ============================================================================
#define AST 40              // A row stride (halfs)

template <int MODE, bool BKM, int MTT>
__global__ __launch_bounds__(128, (BKM ? 4 : 5)) void hgemm(
    int K,
    const __half* __restrict__ A, int lda, long sA,
    const __half* __restrict__ B, int ldb, long sB,
    float* __restrict__ C, int ldc, long sC,
    __half* __restrict__ CH, int ldch, long sCh,
    const float* __restrict__ bias,
    const __half* __restrict__ auxH, int ldaux, long sAux,
    const float* __restrict__ auxF,
    const float* __restrict__ alphaP, int sAlpha,
    const float* __restrict__ rel) {
    constexpr int BST = BKM ? 40 : 136;
    constexpr int ASZ2 = MTT * AST;              // A halfs per stage
    constexpr int BSZ = BKM ? 128 * 40 : 32 * 136;
    constexpr int STG = ASZ2 + BSZ;              // halfs per stage
    constexpr int MI  = MTT / 16;                // m 16-row frags per warp
    constexpr int AITER = (MTT * 4) / 128;       // A 16B copies per thread

    extern __shared__ __half sh[];
    const int z = blockIdx.z;
    A += z * sA; B += z * sB;
    if (MODE == 3 || MODE == 4) C += z * sC;
    if (MODE == 1 || MODE == 2) CH += z * sCh;
    if (MODE == 2) auxH += z * sAux;
    if (MODE == 3) auxF += z * sAux;
    if (MODE == 4) bias += (long)z * LL;
    const float* alpha = (MODE == 3) ? (alphaP + (long)z * sAlpha) : nullptr;

    const int tid = threadIdx.x, wid = tid >> 5, lane = tid & 31;
    const int wn = wid;                          // 4 warps over n (x32 cols)
    const int m0 = blockIdx.y * MTT, n0 = blockIdx.x * 128;
    const uint32_t smb = smem_u32(sh);
    const int nk = K >> 5;

    // ---- ldmatrix base addresses (slot 0, k=0), bytes
    uint32_t aAddr[MI], bAddr[2];
    #pragma unroll
    for (int mi = 0; mi < MI; mi++) {
        int off = (mi * 16 + (lane & 15)) * AST + ((lane >> 4) << 3);
        aAddr[mi] = smb + off * 2;
    }
    #pragma unroll
    for (int p = 0; p < 2; p++) {
        int off;
        if (BKM) // SMEM [n][k]
            off = (wn * 32 + p * 16 + (lane & 7) + ((lane >> 4) << 3)) * BST
                  + (((lane >> 3) & 1) << 3);
        else     // SMEM [k][n]
            off = (lane & 15) * BST + wn * 32 + p * 16 + ((lane >> 4) << 3);
        bAddr[p] = smb + (ASZ2 + off) * 2;
    }

    // ---- stage loader (slot in {0,1,2})
    auto load_stage = [&](int c, int slot) {
        const uint32_t ab = smb + (uint32_t)(slot * STG) * 2;
        const uint32_t bb = ab + ASZ2 * 2;
        #pragma unroll
        for (int i = 0; i < AITER; i++) {                    // A: MTT x 32 halfs
            int v = tid + i * 128;
            int r = v >> 2, ch = v & 3;
            cp16(ab + (uint32_t)(r * AST + ch * 8) * 2,
                 A + (long)(m0 + r) * lda + c * 32 + ch * 8);
        }
        if (BKM) {
            #pragma unroll
            for (int i = 0; i < 4; i++) {                    // B: 128 n-rows x 32 halfs
                int v = tid + i * 128;
                int r = v >> 2, ch = v & 3;
                cp16(bb + (uint32_t)(r * BST + ch * 8) * 2,
                     B + (long)(n0 + r) * ldb + c * 32 + ch * 8);
            }
        } else {
            #pragma unroll
            for (int i = 0; i < 4; i++) {                    // B: 32 k-rows x 128 halfs
                int v = tid + i * 128;
                int r = v >> 4, ch = v & 15;
                cp16(bb + (uint32_t)(r * BST + ch * 8) * 2,
                     B + (long)(c * 32 + r) * ldb + n0 + ch * 8);
            }
        }
    };

    load_stage(0, 0); cp_commit();
    load_stage(1, 1); cp_commit();

    float acc[MI][4][4] = {};
    int cs = 0;                                  // compute slot
    for (int c = 0; c < nk; c++) {
        cp_wait<1>();
        __syncthreads();
        if (c + 2 < nk) {
            int ls = cs + 2; if (ls >= 3) ls -= 3;
            load_stage(c + 2, ls);
        }
        cp_commit();

        const uint32_t so = (uint32_t)(cs * STG) * 2;
        #pragma unroll
        for (int kk = 0; kk < 2; kk++) {
            const int ks = kk * 16;
            uint32_t af[MI][4], bf[4][2];
            #pragma unroll
            for (int mi = 0; mi < MI; mi++)
                ldm_x4(af[mi], aAddr[mi] + so + ks * 2);
            #pragma unroll
            for (int p = 0; p < 2; p++) {
                uint32_t r4[4];
                if (BKM) ldm_x4(r4, bAddr[p] + so + ks * 2);
                else     ldm_x4_t(r4, bAddr[p] + so + ks * (BST * 2));
                bf[2 * p + 0][0] = r4[0]; bf[2 * p + 0][1] = r4[1];
                bf[2 * p + 1][0] = r4[2]; bf[2 * p + 1][1] = r4[3];
            }
            #pragma unroll
            for (int mi = 0; mi < MI; mi++)
                #pragma unroll
                for (int ni = 0; ni < 4; ni++)
                    mma16816(acc[mi][ni], af[mi], bf[ni]);
        }
        if (++cs == 3) cs = 0;
    }

    // ---- epilogue
    const int g = lane >> 2, t2 = (lane & 3) << 1;
    #pragma unroll
    for (int mi = 0; mi < MI; mi++) {
        #pragma unroll
        for (int half = 0; half < 2; half++) {
            long r = m0 + mi * 16 + g + half * 8;
            #pragma unroll
            for (int ni = 0; ni < 4; ni++) {
                int c = n0 + wn * 32 + ni * 8 + t2;
                float v0 = acc[mi][ni][half * 2 + 0];
                float v1 = acc[mi][ni][half * 2 + 1];
                if (MODE == 1) {
                    v0 = siluf(v0 + bias[c]); v1 = siluf(v1 + bias[c + 1]);
                    *(__half2*)(CH + r * (long)ldch + c) = __floats2half2_rn(v0, v1);
                } else if (MODE == 2) {
                    const __half2 gt = *(const __half2*)(auxH + r * (long)ldaux + c);
                    v0 *= __half2float(gt.x); v1 *= __half2float(gt.y);
                    *(__half2*)(CH + r * (long)ldch + c) = __floats2half2_rn(v0, v1);
                } else if (MODE == 3) {
                    const float2 sres = *(const float2*)(auxF + r * (long)ldaux + c);
                    v0 = (v0 + bias[c]) * (1.f + alpha[c]) + sres.x;
                    v1 = (v1 + bias[c + 1]) * (1.f + alpha[c + 1]) + sres.y;
                    *(float2*)(C + r * (long)ldc + c) = make_float2(v0, v1);
                } else {
                    int d0 = (int)r - c;     d0 = d0 < -64 ? -64 : (d0 > 64 ? 64 : d0);
                    int d1 = (int)r - c - 1; d1 = d1 < -64 ? -64 : (d1 > 64 ? 64 : d1);
                    v0 += bias[c] + rel[d0 + 64];
                    v1 += bias[c + 1] + rel[d1 + 64];
                    *(float2*)(C + r * (long)ldc + c) = make_float2(v0, v1);
                }
            }
        }
    }
}

// ---------------- q/k build + RoPE (reads fp16 h) ----------------------------
__global__ void qk_rope_k(const __half* __restrict__ h, const float* __restrict__ mw,
                          const float* __restrict__ mb, const float* __restrict__ scal,
                          __half* __restrict__ q, __half* __restrict__ k) {
    const int row = blockIdx.x;
    const int t   = threadIdx.x;           // 0..127
    const int pos = row & (LL - 1);
    const __half* base = h + (long)row * GVA_N + 2 * PROJ;
    float b0 = __half2float(base[t]), b1 = __half2float(base[t + 128]);
    float q0 = fmaf(b0, mw[t],       mb[t]);
    float q1 = fmaf(b1, mw[t + 128], mb[t + 128]);
    float k0 = fmaf(b0, mw[256 + t],       mb[256 + t]);
    float k1 = fmaf(b1, mw[256 + t + 128], mb[256 + t + 128]);
    float freq = exp2f(-(float)t * (13.287712379549449f / 128.f));
    float ang = (float)pos * freq;
    float sn, cs; sincosf(ang, &sn, &cs);
    float sc = scal[row];
    q[(long)row * 256 + t]       = __float2half_rn((q0 * cs - q1 * sn) * sc);
    q[(long)row * 256 + t + 128] = __float2half_rn((q1 * cs + q0 * sn) * sc);
    k[(long)row * 256 + t]       = __float2half_rn(k0 * cs - k1 * sn);
    k[(long)row * 256 + t + 128] = __float2half_rn(k1 * cs + k0 * sn);
}

// ---------------- row softmax over 1024: fp16 out, fp32 out optional ---------
__global__ __launch_bounds__(256) void softmax_k(float* __restrict__ S,
                                                 __half* __restrict__ S16,
                                                 int write32) {
    float4* p = (float4*)(S + (long)blockIdx.x * LL);
    __half2* p16 = (__half2*)(S16 + (long)blockIdx.x * LL);
    float4 v = p[threadIdx.x];
    __shared__ float rm[8], rs[8];
    float m = fmaxf(fmaxf(v.x, v.y), fmaxf(v.z, v.w));
    m = warpMax(m);
    if ((threadIdx.x & 31) == 0) rm[threadIdx.x >> 5] = m;
    __syncthreads();
    m = rm[0];
    #pragma unroll
    for (int i = 1; i < 8; i++) m = fmaxf(m, rm[i]);
    v.x = __expf(v.x - m); v.y = __expf(v.y - m);
    v.z = __expf(v.z - m); v.w = __expf(v.w - m);
    float s = v.x + v.y + v.z + v.w;
    s = warpSum(s);
    if ((threadIdx.x & 31) == 0) rs[threadIdx.x >> 5] = s;
    __syncthreads();
    s = 0.f;
    #pragma unroll
    for (int i = 0; i < 8; i++) s += rs[i];
    float inv = 1.f / s;
    v.x *= inv; v.y *= inv; v.z *= inv; v.w *= inv;
    if (write32) p[threadIdx.x] = v;
    p16[threadIdx.x * 2 + 0] = __floats2half2_rn(v.x, v.y);
    p16[threadIdx.x * 2 + 1] = __floats2half2_rn(v.z, v.w);
}

// ---------------- edge = attn[0] + attn[1] (fp32) ----------------------------
__global__ void edge_k(const float* __restrict__ attn, float* __restrict__ e) {
    long i = (long)blockIdx.x * 256 + threadIdx.x;
    float4 a = ((const float4*)attn)[i];
    float4 b = ((const float4*)(attn + (long)LL * LL))[i];
    ((float4*)e)[i] = make_float4(a.x + b.x, a.y + b.y, a.z + b.z, a.w + b.w);
}

// ---------------- launch ------------------------------------------------------
extern "C" void kernel_launch(void* const* d_in, const int* in_sizes, int n_in,
                              void* d_out, int out_size) {
    const float* node      = (const float*)d_in[0];
    const float* qk_scal   = (const float*)d_in[1];
    const float* bias      = (const float*)d_in[2];
    const float* cond      = (const float*)d_in[3];
    const float* w_gva     = (const float*)d_in[4];
    const float* b_gva     = (const float*)d_in[5];
    const float* mhs_w     = (const float*)d_in[6];
    const float* mhs_b     = (const float*)d_in[7];
    const float* relpos    = (const float*)d_in[8];
    const float* w_out     = (const float*)d_in[9];
    const float* b_out     = (const float*)d_in[10];
    const float* w_adaln   = (const float*)d_in[11];
    const float* b_adaln   = (const float*)d_in[12];
    float* out = (float*)d_out;

    float *sc, *part, *gba, *attn, *nodeb;
    __half *x16, *h16, *q16, *k16, *attn16, *av16, *wg16, *wo16;
    cudaGetSymbolAddress((void**)&sc,     d_sc);
    cudaGetSymbolAddress((void**)&part,   d_part);
    cudaGetSymbolAddress((void**)&gba,    d_gba);
    cudaGetSymbolAddress((void**)&x16,    d_x16);
    cudaGetSymbolAddress((void**)&h16,    d_h16);
    cudaGetSymbolAddress((void**)&q16,    d_q16);
    cudaGetSymbolAddress((void**)&k16,    d_k16);
    cudaGetSymbolAddress((void**)&attn,   d_attn);
    cudaGetSymbolAddress((void**)&attn16, d_attn16);
    cudaGetSymbolAddress((void**)&av16,   d_av16);
    cudaGetSymbolAddress((void**)&nodeb,  d_node);
    cudaGetSymbolAddress((void**)&wg16,   d_wgva16);
    cudaGetSymbolAddress((void**)&wo16,   d_wout16);

    const int SMW64 = 3 * (64 * AST + 32 * 136) * 2;   // 41472 (GVA, AV)
    const int SMW32 = 3 * (32 * AST + 32 * 136) * 2;   // 33792 (out-proj)
    const int SMK64 = 3 * (64 * AST + 128 * 40) * 2;   // 46080 (logits)
    cudaFuncSetAttribute(hgemm<1, false, 64>, cudaFuncAttributeMaxDynamicSharedMemorySize, SMW64);
    cudaFuncSetAttribute(hgemm<2, false, 64>, cudaFuncAttributeMaxDynamicSharedMemorySize, SMW64);
    cudaFuncSetAttribute(hgemm<3, false, 32>, cudaFuncAttributeMaxDynamicSharedMemorySize, SMW32);
    cudaFuncSetAttribute(hgemm<4, true, 64>,  cudaFuncAttributeMaxDynamicSharedMemorySize, SMK64);

    cudaMemcpyAsync(nodeb, node, (size_t)ROWS * NODE * sizeof(float),
                    cudaMemcpyDeviceToDevice);
    f2h_k<<<(int)((long)NL * NODE * GVA_N / 1024), 256>>>(w_gva, wg16);
    f2h_k<<<(int)((long)NL * PROJ * NODE / 1024), 256>>>(w_out, wo16);

    silu_vec_k<<<(BB * NODE + 255) / 256, 256>>>(cond, sc, BB * NODE);
    adaln_part_k<<<dim3(ADALN_N / 256, BB * KS, NL), 256>>>(sc, w_adaln, part);
    adaln_reduce_k<<<(NL * BB * ADALN_N) / 256, 256>>>(part, b_adaln, gba);

    for (int l = 0; l < NL; l++) {
        const float* gba_l = gba + (long)l * BB * ADALN_N;

        ln_mod_k<<<ROWS, 256>>>(nodeb, gba_l, x16);

        // h16 = silu(x @ w_gva + b_gva)   [2048 x 5376 x 1280]: 1344 CTAs
        hgemm<1, false, 64><<<dim3(GVA_N / 128, ROWS / 64, 1), 128, SMW64>>>(
            NODE,
            x16, NODE, 0L,
            wg16 + (long)l * NODE * GVA_N, GVA_N, 0L,
            nullptr, 0, 0L,
            h16, GVA_N, 0L,
            b_gva + l * GVA_N,
            nullptr, 0, 0L, nullptr, nullptr, 0, nullptr);

        qk_rope_k<<<ROWS, 128>>>(h16, mhs_w + l * 2 * ATTND, mhs_b + l * 2 * ATTND,
                                 qk_scal, q16, k16);

        // logits = q @ k^T + bias + rel   [1024 x 1024 x 256] x2: 256 CTAs
        hgemm<4, true, 64><<<dim3(LL / 128, LL / 64, BB), 128, SMK64>>>(
            ATTND,
            q16, ATTND, (long)LL * ATTND,
            k16, ATTND, (long)LL * ATTND,
            attn, LL, (long)LL * LL,
            nullptr, 0, 0L,
            bias,
            nullptr, 0, 0L, nullptr, nullptr, 0,
            relpos + l * NREL);

        softmax_k<<<ROWS, 256>>>(attn, attn16, (l == NL - 1) ? 1 : 0);

        if (l == NL - 1)
            edge_k<<<(LL * LL / 4) / 256, 256>>>(attn, out + (long)ROWS * NODE);

        // av16 = (attn @ values) * gates   [1024 x 2560 x 1024] x2: 640 CTAs
        hgemm<2, false, 64><<<dim3(PROJ / 128, LL / 64, BB), 128, SMW64>>>(
            LL,
            attn16, LL, (long)LL * LL,
            h16 + PROJ, GVA_N, (long)LL * GVA_N,
            nullptr, 0, 0L,
            av16, PROJ, (long)LL * PROJ,
            nullptr,
            h16, GVA_N, (long)LL * GVA_N,    // gates fp16
            nullptr, nullptr, 0, nullptr);

        // node = (av @ w_out + b_out)*(1+alpha) + shortcut
        // [1024 x 1280 x 2560] x2, MT=32: 640 CTAs (fill 0.86 at occ 5)
        float* Cdst = (l == NL - 1) ? out : nodeb;
        hgemm<3, false, 32><<<dim3(NODE / 128, LL / 32, BB), 128, SMW32>>>(
            PROJ,
            av16, PROJ, (long)LL * PROJ,
            wo16 + (long)l * PROJ * NODE, NODE, 0L,
            Cdst, NODE, (long)LL * NODE,
            nullptr, 0, 0L,
            b_out + l * NODE,
            nullptr, NODE, (long)LL * NODE,
            nodeb,                            // residual fp32
            gba_l + 2 * NODE, ADALN_N, nullptr);
    }
    (void)in_sizes; (void)n_in; (void)out_size;
}

// round 13
// speedup vs baseline: 1.0110x; 1.0110x over previous
#include <cuda_runtime.h>
#include <cuda_fp16.h>
#include <cstdint>
#include <math.h>

#define NODE   1280
#define PROJ   2560
#define ATTND  256
#define NREL   129
#define NL     4
#define BB     2
#define LL     1024
#define GVA_N  (2*PROJ + ATTND)   // 5376
#define ADALN_N (3*NODE)          // 3840
#define ROWS   (BB*LL)            // 2048
#define KS     10                 // adaLN split-K factor

// ---------------- scratch (device globals; no allocation allowed) ----------
__device__ float  d_sc    [BB*NODE];
__device__ float  d_part  [NL*BB*KS*ADALN_N];
__device__ float  d_gba   [NL*BB*ADALN_N];
__device__ __half d_x16   [ROWS*NODE];
__device__ __half d_h16   [ROWS*GVA_N];
__device__ __half d_q16   [ROWS*ATTND];
__device__ __half d_k16   [ROWS*ATTND];
__device__ float  d_attn  [(long)BB*LL*LL];
__device__ __half d_attn16[(long)BB*LL*LL];
__device__ __half d_av16  [ROWS*PROJ];
__device__ float  d_node  [ROWS*NODE];
__device__ __half d_wgva16[(long)NL*NODE*GVA_N];
__device__ __half d_wout16[(long)NL*PROJ*NODE];

// ---------------- helpers ---------------------------------------------------
__device__ __forceinline__ float siluf(float x) { return x / (1.f + __expf(-x)); }
__device__ __forceinline__ float warpMax(float v) {
    #pragma unroll
    for (int o = 16; o > 0; o >>= 1) v = fmaxf(v, __shfl_xor_sync(0xffffffffu, v, o));
    return v;
}
__device__ __forceinline__ float warpSum(float v) {
    #pragma unroll
    for (int o = 16; o > 0; o >>= 1) v += __shfl_xor_sync(0xffffffffu, v, o);
    return v;
}
__device__ __forceinline__ uint32_t smem_u32(const void* p) {
    uint32_t a;
    asm("{ .reg .u64 t; cvta.to.shared.u64 t, %1; cvt.u32.u64 %0, t; }"
        : "=r"(a) : "l"(p));
    return a;
}
__device__ __forceinline__ void cp16(uint32_t dst, const void* src) {
    asm volatile("cp.async.cg.shared.global [%0], [%1], 16;" :: "r"(dst), "l"(src));
}
__device__ __forceinline__ void cp_commit() {
    asm volatile("cp.async.commit_group;" ::: "memory");
}
template <int N>
__device__ __forceinline__ void cp_wait() {
    asm volatile("cp.async.wait_group %0;" :: "n"(N) : "memory");
}
__device__ __forceinline__ void ldm_x4(uint32_t* r, uint32_t a) {
    asm volatile("ldmatrix.sync.aligned.m8n8.x4.shared.b16 {%0,%1,%2,%3}, [%4];"
                 : "=r"(r[0]), "=r"(r[1]), "=r"(r[2]), "=r"(r[3]) : "r"(a));
}
__device__ __forceinline__ void ldm_x4_t(uint32_t* r, uint32_t a) {
    asm volatile("ldmatrix.sync.aligned.m8n8.x4.trans.shared.b16 {%0,%1,%2,%3}, [%4];"
                 : "=r"(r[0]), "=r"(r[1]), "=r"(r[2]), "=r"(r[3]) : "r"(a));
}
__device__ __forceinline__ void mma16816(float* c, const uint32_t* a, const uint32_t* b) {
    asm volatile(
        "mma.sync.aligned.m16n8k16.row.col.f32.f16.f16.f32 "
        "{%0,%1,%2,%3}, {%4,%5,%6,%7}, {%8,%9}, {%0,%1,%2,%3};"
        : "+f"(c[0]), "+f"(c[1]), "+f"(c[2]), "+f"(c[3])
        : "r"(a[0]), "r"(a[1]), "r"(a[2]), "r"(a[3]), "r"(b[0]), "r"(b[1]));
}

// ---------------- small kernels ---------------------------------------------
__global__ void silu_vec_k(const float* __restrict__ c, float* __restrict__ sc, int n) {
    int i = blockIdx.x * 256 + threadIdx.x;
    if (i < n) sc[i] = siluf(c[i]);
}

__global__ void f2h_k(const float* __restrict__ in, __half* __restrict__ out) {
    long i = (long)blockIdx.x * 256 + threadIdx.x;
    float4 v = ((const float4*)in)[i];
    ((__half2*)out)[2 * i]     = __floats2half2_rn(v.x, v.y);
    ((__half2*)out)[2 * i + 1] = __floats2half2_rn(v.z, v.w);
}

__global__ void adaln_part_k(const float* __restrict__ sc, const float* __restrict__ w,
                             float* __restrict__ part) {
    const int l = blockIdx.z;
    const int b = blockIdx.y / KS, ks = blockIdx.y % KS;
    const int col = blockIdx.x * 256 + threadIdx.x;
    const int KC = NODE / KS;                  // 128
    const float* s  = sc + b * NODE + ks * KC;
    const float* wp = w + (long)l * NODE * ADALN_N + (long)ks * KC * ADALN_N + col;
    float a0 = 0.f, a1 = 0.f, a2 = 0.f, a3 = 0.f;
    #pragma unroll 4
    for (int k = 0; k < KC; k += 4) {
        a0 = fmaf(s[k],     wp[(long)k * ADALN_N],       a0);
        a1 = fmaf(s[k + 1], wp[(long)(k + 1) * ADALN_N], a1);
        a2 = fmaf(s[k + 2], wp[(long)(k + 2) * ADALN_N], a2);
        a3 = fmaf(s[k + 3], wp[(long)(k + 3) * ADALN_N], a3);
    }
    part[((((long)l * BB) + b) * KS + ks) * ADALN_N + col] = (a0 + a1) + (a2 + a3);
}
__global__ void adaln_reduce_k(const float* __restrict__ part,
                               const float* __restrict__ bvec, float* __restrict__ gba) {
    long idx = (long)blockIdx.x * 256 + threadIdx.x;
    int l = (int)(idx / (BB * ADALN_N));
    int rem = (int)(idx % (BB * ADALN_N));
    int b = rem / ADALN_N, col = rem % ADALN_N;
    const float* p = part + (((long)l * BB + b) * KS) * ADALN_N + col;
    float acc = bvec[l * ADALN_N + col];
    #pragma unroll
    for (int i = 0; i < KS; i++) acc += p[(long)i * ADALN_N];
    gba[idx] = acc;
}

// LayerNorm + modulate -> fp16 x
__global__ __launch_bounds__(256) void ln_mod_k(const float* __restrict__ node,
                                                const float* __restrict__ gba,
                                                __half* __restrict__ x16) {
    const int row = blockIdx.x;
    const int b   = row >> 10;
    const float* p = node + (long)row * NODE;
    float vals[5];
    float s = 0.f, sq = 0.f;
    #pragma unroll
    for (int i = 0; i < 5; i++) {
        float v = p[threadIdx.x + i * 256];
        vals[i] = v; s += v; sq += v * v;
    }
    __shared__ float rs[8], rq[8];
    s = warpSum(s); sq = warpSum(sq);
    if ((threadIdx.x & 31) == 0) { rs[threadIdx.x >> 5] = s; rq[threadIdx.x >> 5] = sq; }
    __syncthreads();
    float ts = 0.f, tq = 0.f;
    #pragma unroll
    for (int i = 0; i < 8; i++) { ts += rs[i]; tq += rq[i]; }
    const float mean = ts * (1.f / NODE);
    const float var  = tq * (1.f / NODE) - mean * mean;
    const float rstd = rsqrtf(var + 1e-5f);
    const float* g = gba + (long)b * ADALN_N;
    __half* xo = x16 + (long)row * NODE;
    #pragma unroll
    for (int i = 0; i < 5; i++) {
        int c = threadIdx.x + i * 256;
        float v = (vals[i] - mean) * rstd;
        xo[c] = __float2half_rn(v * (1.f + g[c]) + g[NODE + c]);
    }
}

// ============================================================================
// fp16 mma.sync GEMM: CTA tile MTT x 128, 128 threads (4 warps, MTTx32 warp
// tile), BK=32, 3-stage cp.async pipeline, high occupancy.
// ============================================================================
#define AST 40              // A row stride (halfs)

template <int MODE, bool BKM, int MTT>
__global__ __launch_bounds__(128, (BKM ? 4 : 5)) void hgemm(
    int K,
    const __half* __restrict__ A, int lda, long sA,
    const __half* __restrict__ B, int ldb, long sB,
    float* __restrict__ C, int ldc, long sC,
    __half* __restrict__ CH, int ldch, long sCh,
    const float* __restrict__ bias,
    const __half* __restrict__ auxH, int ldaux, long sAux,
    const float* __restrict__ auxF,
    const float* __restrict__ alphaP, int sAlpha,
    const float* __restrict__ rel) {
    constexpr int BST = BKM ? 40 : 136;
    constexpr int ASZ2 = MTT * AST;
    constexpr int BSZ = BKM ? 128 * 40 : 32 * 136;
    constexpr int STG = ASZ2 + BSZ;
    constexpr int MI  = MTT / 16;
    constexpr int AITER = (MTT * 4) / 128;

    extern __shared__ __half sh[];
    const int z = blockIdx.z;
    A += z * sA; B += z * sB;
    if (MODE == 3 || MODE == 4) C += z * sC;
    if (MODE == 1 || MODE == 2) CH += z * sCh;
    if (MODE == 2) auxH += z * sAux;
    if (MODE == 3) auxF += z * sAux;
    if (MODE == 4) bias += (long)z * LL;
    const float* alpha = (MODE == 3) ? (alphaP + (long)z * sAlpha) : nullptr;

    const int tid = threadIdx.x, wid = tid >> 5, lane = tid & 31;
    const int wn = wid;
    const int m0 = blockIdx.y * MTT, n0 = blockIdx.x * 128;
    const uint32_t smb = smem_u32(sh);
    const int nk = K >> 5;

    uint32_t aAddr[MI], bAddr[2];
    #pragma unroll
    for (int mi = 0; mi < MI; mi++) {
        int off = (mi * 16 + (lane & 15)) * AST + ((lane >> 4) << 3);
        aAddr[mi] = smb + off * 2;
    }
    #pragma unroll
    for (int p = 0; p < 2; p++) {
        int off;
        if (BKM)
            off = (wn * 32 + p * 16 + (lane & 7) + ((lane >> 4) << 3)) * BST
                  + (((lane >> 3) & 1) << 3);
        else
            off = (lane & 15) * BST + wn * 32 + p * 16 + ((lane >> 4) << 3);
        bAddr[p] = smb + (ASZ2 + off) * 2;
    }

    auto load_stage = [&](int c, int slot) {
        const uint32_t ab = smb + (uint32_t)(slot * STG) * 2;
        const uint32_t bb = ab + ASZ2 * 2;
        #pragma unroll
        for (int i = 0; i < AITER; i++) {
            int v = tid + i * 128;
            int r = v >> 2, ch = v & 3;
            cp16(ab + (uint32_t)(r * AST + ch * 8) * 2,
                 A + (long)(m0 + r) * lda + c * 32 + ch * 8);
        }
        if (BKM) {
            #pragma unroll
            for (int i = 0; i < 4; i++) {
                int v = tid + i * 128;
                int r = v >> 2, ch = v & 3;
                cp16(bb + (uint32_t)(r * BST + ch * 8) * 2,
                     B + (long)(n0 + r) * ldb + c * 32 + ch * 8);
            }
        } else {
            #pragma unroll
            for (int i = 0; i < 4; i++) {
                int v = tid + i * 128;
                int r = v >> 4, ch = v & 15;
                cp16(bb + (uint32_t)(r * BST + ch * 8) * 2,
                     B + (long)(c * 32 + r) * ldb + n0 + ch * 8);
            }
        }
    };

    load_stage(0, 0); cp_commit();
    load_stage(1, 1); cp_commit();

    float acc[MI][4][4] = {};
    int cs = 0;
    for (int c = 0; c < nk; c++) {
        cp_wait<1>();
        __syncthreads();
        if (c + 2 < nk) {
            int ls = cs + 2; if (ls >= 3) ls -= 3;
            load_stage(c + 2, ls);
        }
        cp_commit();

        const uint32_t so = (uint32_t)(cs * STG) * 2;
        #pragma unroll
        for (int kk = 0; kk < 2; kk++) {
            const int ks = kk * 16;
            uint32_t af[MI][4], bf[4][2];
            #pragma unroll
            for (int mi = 0; mi < MI; mi++)
                ldm_x4(af[mi], aAddr[mi] + so + ks * 2);
            #pragma unroll
            for (int p = 0; p < 2; p++) {
                uint32_t r4[4];
                if (BKM) ldm_x4(r4, bAddr[p] + so + ks * 2);
                else     ldm_x4_t(r4, bAddr[p] + so + ks * (BST * 2));
                bf[2 * p + 0][0] = r4[0]; bf[2 * p + 0][1] = r4[1];
                bf[2 * p + 1][0] = r4[2]; bf[2 * p + 1][1] = r4[3];
            }
            #pragma unroll
            for (int mi = 0; mi < MI; mi++)
                #pragma unroll
                for (int ni = 0; ni < 4; ni++)
                    mma16816(acc[mi][ni], af[mi], bf[ni]);
        }
        if (++cs == 3) cs = 0;
    }

    const int g = lane >> 2, t2 = (lane & 3) << 1;
    #pragma unroll
    for (int mi = 0; mi < MI; mi++) {
        #pragma unroll
        for (int half = 0; half < 2; half++) {
            long r = m0 + mi * 16 + g + half * 8;
            #pragma unroll
            for (int ni = 0; ni < 4; ni++) {
                int c = n0 + wn * 32 + ni * 8 + t2;
                float v0 = acc[mi][ni][half * 2 + 0];
                float v1 = acc[mi][ni][half * 2 + 1];
                if (MODE == 1) {
                    v0 = siluf(v0 + bias[c]); v1 = siluf(v1 + bias[c + 1]);
                    *(__half2*)(CH + r * (long)ldch + c) = __floats2half2_rn(v0, v1);
                } else if (MODE == 2) {
                    const __half2 gt = *(const __half2*)(auxH + r * (long)ldaux + c);
                    v0 *= __half2float(gt.x); v1 *= __half2float(gt.y);
                    *(__half2*)(CH + r * (long)ldch + c) = __floats2half2_rn(v0, v1);
                } else if (MODE == 3) {
                    const float2 sres = *(const float2*)(auxF + r * (long)ldaux + c);
                    v0 = (v0 + bias[c]) * (1.f + alpha[c]) + sres.x;
                    v1 = (v1 + bias[c + 1]) * (1.f + alpha[c + 1]) + sres.y;
                    *(float2*)(C + r * (long)ldc + c) = make_float2(v0, v1);
                } else {
                    int d0 = (int)r - c;     d0 = d0 < -64 ? -64 : (d0 > 64 ? 64 : d0);
                    int d1 = (int)r - c - 1; d1 = d1 < -64 ? -64 : (d1 > 64 ? 64 : d1);
                    v0 += bias[c] + rel[d0 + 64];
                    v1 += bias[c + 1] + rel[d1 + 64];
                    *(float2*)(C + r * (long)ldc + c) = make_float2(v0, v1);
                }
            }
        }
    }
}

// ---------------- q/k build + RoPE (reads fp16 h) ----------------------------
__global__ void qk_rope_k(const __half* __restrict__ h, const float* __restrict__ mw,
                          const float* __restrict__ mb, const float* __restrict__ scal,
                          __half* __restrict__ q, __half* __restrict__ k) {
    const int row = blockIdx.x;
    const int t   = threadIdx.x;
    const int pos = row & (LL - 1);
    const __half* base = h + (long)row * GVA_N + 2 * PROJ;
    float b0 = __half2float(base[t]), b1 = __half2float(base[t + 128]);
    float q0 = fmaf(b0, mw[t],       mb[t]);
    float q1 = fmaf(b1, mw[t + 128], mb[t + 128]);
    float k0 = fmaf(b0, mw[256 + t],       mb[256 + t]);
    float k1 = fmaf(b1, mw[256 + t + 128], mb[256 + t + 128]);
    float freq = exp2f(-(float)t * (13.287712379549449f / 128.f));
    float ang = (float)pos * freq;
    float sn, cs; sincosf(ang, &sn, &cs);
    float sc = scal[row];
    q[(long)row * 256 + t]       = __float2half_rn((q0 * cs - q1 * sn) * sc);
    q[(long)row * 256 + t + 128] = __float2half_rn((q1 * cs + q0 * sn) * sc);
    k[(long)row * 256 + t]       = __float2half_rn(k0 * cs - k1 * sn);
    k[(long)row * 256 + t + 128] = __float2half_rn(k1 * cs + k0 * sn);
}

// ---------------- row softmax over 1024 --------------------------------------
__global__ __launch_bounds__(256) void softmax_k(float* __restrict__ S,
                                                 __half* __restrict__ S16,
                                                 int write32) {
    float4* p = (float4*)(S + (long)blockIdx.x * LL);
    __half2* p16 = (__half2*)(S16 + (long)blockIdx.x * LL);
    float4 v = p[threadIdx.x];
    __shared__ float rm[8], rs[8];
    float m = fmaxf(fmaxf(v.x, v.y), fmaxf(v.z, v.w));
    m = warpMax(m);
    if ((threadIdx.x & 31) == 0) rm[threadIdx.x >> 5] = m;
    __syncthreads();
    m = rm[0];
    #pragma unroll
    for (int i = 1; i < 8; i++) m = fmaxf(m, rm[i]);
    v.x = __expf(v.x - m); v.y = __expf(v.y - m);
    v.z = __expf(v.z - m); v.w = __expf(v.w - m);
    float s = v.x + v.y + v.z + v.w;
    s = warpSum(s);
    if ((threadIdx.x & 31) == 0) rs[threadIdx.x >> 5] = s;
    __syncthreads();
    s = 0.f;
    #pragma unroll
    for (int i = 0; i < 8; i++) s += rs[i];
    float inv = 1.f / s;
    v.x *= inv; v.y *= inv; v.z *= inv; v.w *= inv;
    if (write32) p[threadIdx.x] = v;
    p16[threadIdx.x * 2 + 0] = __floats2half2_rn(v.x, v.y);
    p16[threadIdx.x * 2 + 1] = __floats2half2_rn(v.z, v.w);
}

// ---------------- edge = attn[0] + attn[1] (fp32) ----------------------------
__global__ void edge_k(const float* __restrict__ attn, float* __restrict__ e) {
    long i = (long)blockIdx.x * 256 + threadIdx.x;
    float4 a = ((const float4*)attn)[i];
    float4 b = ((const float4*)(attn + (long)LL * LL))[i];
    ((float4*)e)[i] = make_float4(a.x + b.x, a.y + b.y, a.z + b.z, a.w + b.w);
}

// ---------------- launch ------------------------------------------------------
extern "C" void kernel_launch(void* const* d_in, const int* in_sizes, int n_in,
                              void* d_out, int out_size) {
    const float* node      = (const float*)d_in[0];
    const float* qk_scal   = (const float*)d_in[1];
    const float* bias      = (const float*)d_in[2];
    const float* cond      = (const float*)d_in[3];
    const float* w_gva     = (const float*)d_in[4];
    const float* b_gva     = (const float*)d_in[5];
    const float* mhs_w     = (const float*)d_in[6];
    const float* mhs_b     = (const float*)d_in[7];
    const float* relpos    = (const float*)d_in[8];
    const float* w_out     = (const float*)d_in[9];
    const float* b_out     = (const float*)d_in[10];
    const float* w_adaln   = (const float*)d_in[11];
    const float* b_adaln   = (const float*)d_in[12];
    float* out = (float*)d_out;

    float *sc, *part, *gba, *attn, *nodeb;
    __half *x16, *h16, *q16, *k16, *attn16, *av16, *wg16, *wo16;
    cudaGetSymbolAddress((void**)&sc,     d_sc);
    cudaGetSymbolAddress((void**)&part,   d_part);
    cudaGetSymbolAddress((void**)&gba,    d_gba);
    cudaGetSymbolAddress((void**)&x16,    d_x16);
    cudaGetSymbolAddress((void**)&h16,    d_h16);
    cudaGetSymbolAddress((void**)&q16,    d_q16);
    cudaGetSymbolAddress((void**)&k16,    d_k16);
    cudaGetSymbolAddress((void**)&attn,   d_attn);
    cudaGetSymbolAddress((void**)&attn16, d_attn16);
    cudaGetSymbolAddress((void**)&av16,   d_av16);
    cudaGetSymbolAddress((void**)&nodeb,  d_node);
    cudaGetSymbolAddress((void**)&wg16,   d_wgva16);
    cudaGetSymbolAddress((void**)&wo16,   d_wout16);

    // side stream + events for overlapping weight conversion with layer-0 math.
    // Created once on the (uncaptured) correctness call; reused during capture.
    static cudaStream_t s2 = nullptr;
    static cudaEvent_t evFork = nullptr, evJoin = nullptr;
    if (s2 == nullptr) {
        cudaStreamCreateWithFlags(&s2, cudaStreamNonBlocking);
        cudaEventCreateWithFlags(&evFork, cudaEventDisableTiming);
        cudaEventCreateWithFlags(&evJoin, cudaEventDisableTiming);
    }

    const int SMW64 = 3 * (64 * AST + 32 * 136) * 2;   // 41472
    const int SMK64 = 3 * (64 * AST + 128 * 40) * 2;   // 46080
    cudaFuncSetAttribute(hgemm<1, false, 64>, cudaFuncAttributeMaxDynamicSharedMemorySize, SMW64);
    cudaFuncSetAttribute(hgemm<2, false, 64>, cudaFuncAttributeMaxDynamicSharedMemorySize, SMW64);
    cudaFuncSetAttribute(hgemm<3, false, 64>, cudaFuncAttributeMaxDynamicSharedMemorySize, SMW64);
    cudaFuncSetAttribute(hgemm<4, true, 64>,  cudaFuncAttributeMaxDynamicSharedMemorySize, SMK64);

    const long WGL = (long)NODE * GVA_N;               // wgva elems per layer

    cudaMemcpyAsync(nodeb, node, (size_t)ROWS * NODE * sizeof(float),
                    cudaMemcpyDeviceToDevice);
    silu_vec_k<<<(BB * NODE + 255) / 256, 256>>>(cond, sc, BB * NODE);
    adaln_part_k<<<dim3(ADALN_N / 256, BB * KS, NL), 256>>>(sc, w_adaln, part);
    adaln_reduce_k<<<(NL * BB * ADALN_N) / 256, 256>>>(part, b_adaln, gba);
    // layer-0 GVA weights on the critical path
    f2h_k<<<(int)(WGL / 1024), 256>>>(w_gva, wg16);

    // fork: bulk conversions on s2, overlapped with layer-0 ln/GVA/attention
    cudaEventRecord(evFork, 0);
    cudaStreamWaitEvent(s2, evFork, 0);
    f2h_k<<<(int)(3 * WGL / 1024), 256, 0, s2>>>(w_gva + WGL, wg16 + WGL);
    f2h_k<<<(int)((long)NL * PROJ * NODE / 1024), 256, 0, s2>>>(w_out, wo16);
    cudaEventRecord(evJoin, s2);

    bool joined = false;
    for (int l = 0; l < NL; l++) {
        const float* gba_l = gba + (long)l * BB * ADALN_N;

        ln_mod_k<<<ROWS, 256>>>(nodeb, gba_l, x16);

        // h16 = silu(x @ w_gva + b_gva)   [2048 x 5376 x 1280]
        hgemm<1, false, 64><<<dim3(GVA_N / 128, ROWS / 64, 1), 128, SMW64>>>(
            NODE,
            x16, NODE, 0L,
            wg16 + (long)l * WGL, GVA_N, 0L,
            nullptr, 0, 0L,
            h16, GVA_N, 0L,
            b_gva + l * GVA_N,
            nullptr, 0, 0L, nullptr, nullptr, 0, nullptr);

        qk_rope_k<<<ROWS, 128>>>(h16, mhs_w + l * 2 * ATTND, mhs_b + l * 2 * ATTND,
                                 qk_scal, q16, k16);

        // logits = q @ k^T + bias + rel
        hgemm<4, true, 64><<<dim3(LL / 128, LL / 64, BB), 128, SMK64>>>(
            ATTND,
            q16, ATTND, (long)LL * ATTND,
            k16, ATTND, (long)LL * ATTND,
            attn, LL, (long)LL * LL,
            nullptr, 0, 0L,
            bias,
            nullptr, 0, 0L, nullptr, nullptr, 0,
            relpos + l * NREL);

        softmax_k<<<ROWS, 256>>>(attn, attn16, (l == NL - 1) ? 1 : 0);

        if (l == NL - 1)
            edge_k<<<(LL * LL / 4) / 256, 256>>>(attn, out + (long)ROWS * NODE);

        // av16 = (attn @ values) * gates
        hgemm<2, false, 64><<<dim3(PROJ / 128, LL / 64, BB), 128, SMW64>>>(
            LL,
            attn16, LL, (long)LL * LL,
            h16 + PROJ, GVA_N, (long)LL * GVA_N,
            nullptr, 0, 0L,
            av16, PROJ, (long)LL * PROJ,
            nullptr,
            h16, GVA_N, (long)LL * GVA_N,
            nullptr, nullptr, 0, nullptr);

        // join before the first consumer of wo16 / wg16 layers 1-3
        if (!joined) {
            cudaStreamWaitEvent(0, evJoin, 0);
            joined = true;
        }

        // node = (av @ w_out + b_out)*(1+alpha) + shortcut  (MT=64, reverted)
        float* Cdst = (l == NL - 1) ? out : nodeb;
        hgemm<3, false, 64><<<dim3(NODE / 128, LL / 64, BB), 128, SMW64>>>(
            PROJ,
            av16, PROJ, (long)LL * PROJ,
            wo16 + (long)l * PROJ * NODE, NODE, 0L,
            Cdst, NODE, (long)LL * NODE,
            nullptr, 0, 0L,
            b_out + l * NODE,
            nullptr, NODE, (long)LL * NODE,
            nodeb,
            gba_l + 2 * NODE, ADALN_N, nullptr);
    }
    (void)in_sizes; (void)n_in; (void)out_size;
}

// round 14
// speedup vs baseline: 1.0211x; 1.0099x over previous
#include <cuda_runtime.h>
#include <cuda_fp16.h>
#include <cstdint>
#include <math.h>

#define NODE   1280
#define PROJ   2560
#define ATTND  256
#define NREL   129
#define NL     4
#define BB     2
#define LL     1024
#define GVA_N  (2*PROJ + ATTND)   // 5376
#define ADALN_N (3*NODE)          // 3840
#define ROWS   (BB*LL)            // 2048
#define KS     10                 // adaLN split-K factor

// ---------------- scratch (device globals; no allocation allowed) ----------
__device__ float  d_sc    [BB*NODE];
__device__ float  d_part  [NL*BB*KS*ADALN_N];
__device__ float  d_gba   [NL*BB*ADALN_N];
__device__ __half d_x16   [ROWS*NODE];
__device__ __half d_h16   [ROWS*GVA_N];
__device__ __half d_q16   [ROWS*ATTND];
__device__ __half d_k16   [ROWS*ATTND];
__device__ float  d_attn  [(long)BB*LL*LL];
__device__ __half d_attn16[(long)BB*LL*LL];
__device__ __half d_av16  [ROWS*PROJ];
__device__ float  d_node  [ROWS*NODE];
__device__ __half d_wgva16[(long)NL*NODE*GVA_N];
__device__ __half d_wout16[(long)NL*PROJ*NODE];

// ---------------- helpers ---------------------------------------------------
__device__ __forceinline__ float siluf(float x) { return x / (1.f + __expf(-x)); }
__device__ __forceinline__ float warpMax(float v) {
    #pragma unroll
    for (int o = 16; o > 0; o >>= 1) v = fmaxf(v, __shfl_xor_sync(0xffffffffu, v, o));
    return v;
}
__device__ __forceinline__ float warpSum(float v) {
    #pragma unroll
    for (int o = 16; o > 0; o >>= 1) v += __shfl_xor_sync(0xffffffffu, v, o);
    return v;
}
__device__ __forceinline__ uint32_t smem_u32(const void* p) {
    uint32_t a;
    asm("{ .reg .u64 t; cvta.to.shared.u64 t, %1; cvt.u32.u64 %0, t; }"
        : "=r"(a) : "l"(p));
    return a;
}
__device__ __forceinline__ void cp16(uint32_t dst, const void* src) {
    asm volatile("cp.async.cg.shared.global [%0], [%1], 16;" :: "r"(dst), "l"(src));
}
__device__ __forceinline__ void cp_commit() {
    asm volatile("cp.async.commit_group;" ::: "memory");
}
template <int N>
__device__ __forceinline__ void cp_wait() {
    asm volatile("cp.async.wait_group %0;" :: "n"(N) : "memory");
}
__device__ __forceinline__ void ldm_x4(uint32_t* r, uint32_t a) {
    asm volatile("ldmatrix.sync.aligned.m8n8.x4.shared.b16 {%0,%1,%2,%3}, [%4];"
                 : "=r"(r[0]), "=r"(r[1]), "=r"(r[2]), "=r"(r[3]) : "r"(a));
}
__device__ __forceinline__ void ldm_x4_t(uint32_t* r, uint32_t a) {
    asm volatile("ldmatrix.sync.aligned.m8n8.x4.trans.shared.b16 {%0,%1,%2,%3}, [%4];"
                 : "=r"(r[0]), "=r"(r[1]), "=r"(r[2]), "=r"(r[3]) : "r"(a));
}
__device__ __forceinline__ void mma16816(float* c, const uint32_t* a, const uint32_t* b) {
    asm volatile(
        "mma.sync.aligned.m16n8k16.row.col.f32.f16.f16.f32 "
        "{%0,%1,%2,%3}, {%4,%5,%6,%7}, {%8,%9}, {%0,%1,%2,%3};"
        : "+f"(c[0]), "+f"(c[1]), "+f"(c[2]), "+f"(c[3])
        : "r"(a[0]), "r"(a[1]), "r"(a[2]), "r"(a[3]), "r"(b[0]), "r"(b[1]));
}

// ---------------- small kernels ---------------------------------------------
__global__ void silu_vec_k(const float* __restrict__ c, float* __restrict__ sc, int n) {
    int i = blockIdx.x * 256 + threadIdx.x;
    if (i < n) sc[i] = siluf(c[i]);
}

__global__ void f2h_k(const float* __restrict__ in, __half* __restrict__ out) {
    long i = (long)blockIdx.x * 256 + threadIdx.x;
    float4 v = ((const float4*)in)[i];
    ((__half2*)out)[2 * i]     = __floats2half2_rn(v.x, v.y);
    ((__half2*)out)[2 * i + 1] = __floats2half2_rn(v.z, v.w);
}

__global__ void adaln_part_k(const float* __restrict__ sc, const float* __restrict__ w,
                             float* __restrict__ part) {
    const int l = blockIdx.z;
    const int b = blockIdx.y / KS, ks = blockIdx.y % KS;
    const int col = blockIdx.x * 256 + threadIdx.x;
    const int KC = NODE / KS;                  // 128
    const float* s  = sc + b * NODE + ks * KC;
    const float* wp = w + (long)l * NODE * ADALN_N + (long)ks * KC * ADALN_N + col;
    float a0 = 0.f, a1 = 0.f, a2 = 0.f, a3 = 0.f;
    #pragma unroll 4
    for (int k = 0; k < KC; k += 4) {
        a0 = fmaf(s[k],     wp[(long)k * ADALN_N],       a0);
        a1 = fmaf(s[k + 1], wp[(long)(k + 1) * ADALN_N], a1);
        a2 = fmaf(s[k + 2], wp[(long)(k + 2) * ADALN_N], a2);
        a3 = fmaf(s[k + 3], wp[(long)(k + 3) * ADALN_N], a3);
    }
    part[((((long)l * BB) + b) * KS + ks) * ADALN_N + col] = (a0 + a1) + (a2 + a3);
}
__global__ void adaln_reduce_k(const float* __restrict__ part,
                               const float* __restrict__ bvec, float* __restrict__ gba) {
    long idx = (long)blockIdx.x * 256 + threadIdx.x;
    int l = (int)(idx / (BB * ADALN_N));
    int rem = (int)(idx % (BB * ADALN_N));
    int b = rem / ADALN_N, col = rem % ADALN_N;
    const float* p = part + (((long)l * BB + b) * KS) * ADALN_N + col;
    float acc = bvec[l * ADALN_N + col];
    #pragma unroll
    for (int i = 0; i < KS; i++) acc += p[(long)i * ADALN_N];
    gba[idx] = acc;
}

// LayerNorm + modulate -> fp16 x
__global__ __launch_bounds__(256) void ln_mod_k(const float* __restrict__ node,
                                                const float* __restrict__ gba,
                                                __half* __restrict__ x16) {
    const int row = blockIdx.x;
    const int b   = row >> 10;
    const float* p = node + (long)row * NODE;
    float vals[5];
    float s = 0.f, sq = 0.f;
    #pragma unroll
    for (int i = 0; i < 5; i++) {
        float v = p[threadIdx.x + i * 256];
        vals[i] = v; s += v; sq += v * v;
    }
    __shared__ float rs[8], rq[8];
    s = warpSum(s); sq = warpSum(sq);
    if ((threadIdx.x & 31) == 0) { rs[threadIdx.x >> 5] = s; rq[threadIdx.x >> 5] = sq; }
    __syncthreads();
    float ts = 0.f, tq = 0.f;
    #pragma unroll
    for (int i = 0; i < 8; i++) { ts += rs[i]; tq += rq[i]; }
    const float mean = ts * (1.f / NODE);
    const float var  = tq * (1.f / NODE) - mean * mean;
    const float rstd = rsqrtf(var + 1e-5f);
    const float* g = gba + (long)b * ADALN_N;
    __half* xo = x16 + (long)row * NODE;
    #pragma unroll
    for (int i = 0; i < 5; i++) {
        int c = threadIdx.x + i * 256;
        float v = (vals[i] - mean) * rstd;
        xo[c] = __float2half_rn(v * (1.f + g[c]) + g[NODE + c]);
    }
}

// ============================================================================
// fp16 mma.sync GEMM: CTA tile 64 x 128, 128 threads (4 warps, 64x32 warp
// tile), BK=32, 3-stage cp.async pipeline, high occupancy. Mainloop issues
// kk=0 MMAs before the next-stage cp.async burst to spread LSU issue.
// ============================================================================
#define AST 40              // A row stride (halfs)
#define MTT 64

template <int MODE, bool BKM>
__global__ __launch_bounds__(128, (BKM ? 4 : 5)) void hgemm(
    int K,
    const __half* __restrict__ A, int lda, long sA,
    const __half* __restrict__ B, int ldb, long sB,
    float* __restrict__ C, int ldc, long sC,
    __half* __restrict__ CH, int ldch, long sCh,
    const float* __restrict__ bias,
    const __half* __restrict__ auxH, int ldaux, long sAux,
    const float* __restrict__ auxF,
    const float* __restrict__ alphaP, int sAlpha,
    const float* __restrict__ rel) {
    constexpr int BST = BKM ? 40 : 136;
    constexpr int ASZ2 = MTT * AST;
    constexpr int BSZ = BKM ? 128 * 40 : 32 * 136;
    constexpr int STG = ASZ2 + BSZ;

    extern __shared__ __half sh[];
    const int z = blockIdx.z;
    A += z * sA; B += z * sB;
    if (MODE == 3 || MODE == 4) C += z * sC;
    if (MODE == 1 || MODE == 2) CH += z * sCh;
    if (MODE == 2) auxH += z * sAux;
    if (MODE == 3) auxF += z * sAux;
    if (MODE == 4) bias += (long)z * LL;
    const float* alpha = (MODE == 3) ? (alphaP + (long)z * sAlpha) : nullptr;

    const int tid = threadIdx.x, wid = tid >> 5, lane = tid & 31;
    const int wn = wid;
    const int m0 = blockIdx.y * MTT, n0 = blockIdx.x * 128;
    const uint32_t smb = smem_u32(sh);
    const int nk = K >> 5;

    uint32_t aAddr[4], bAddr[2];
    #pragma unroll
    for (int mi = 0; mi < 4; mi++) {
        int off = (mi * 16 + (lane & 15)) * AST + ((lane >> 4) << 3);
        aAddr[mi] = smb + off * 2;
    }
    #pragma unroll
    for (int p = 0; p < 2; p++) {
        int off;
        if (BKM)
            off = (wn * 32 + p * 16 + (lane & 7) + ((lane >> 4) << 3)) * BST
                  + (((lane >> 3) & 1) << 3);
        else
            off = (lane & 15) * BST + wn * 32 + p * 16 + ((lane >> 4) << 3);
        bAddr[p] = smb + (ASZ2 + off) * 2;
    }

    auto load_stage = [&](int c, int slot) {
        const uint32_t ab = smb + (uint32_t)(slot * STG) * 2;
        const uint32_t bb = ab + ASZ2 * 2;
        #pragma unroll
        for (int i = 0; i < 2; i++) {
            int v = tid + i * 128;
            int r = v >> 2, ch = v & 3;
            cp16(ab + (uint32_t)(r * AST + ch * 8) * 2,
                 A + (long)(m0 + r) * lda + c * 32 + ch * 8);
        }
        if (BKM) {
            #pragma unroll
            for (int i = 0; i < 4; i++) {
                int v = tid + i * 128;
                int r = v >> 2, ch = v & 3;
                cp16(bb + (uint32_t)(r * BST + ch * 8) * 2,
                     B + (long)(n0 + r) * ldb + c * 32 + ch * 8);
            }
        } else {
            #pragma unroll
            for (int i = 0; i < 4; i++) {
                int v = tid + i * 128;
                int r = v >> 4, ch = v & 15;
                cp16(bb + (uint32_t)(r * BST + ch * 8) * 2,
                     B + (long)(c * 32 + r) * ldb + n0 + ch * 8);
            }
        }
    };

    auto do_kk = [&](uint32_t so, int ks, float (*acc)[4][4]) {
        uint32_t af[4][4], bf[4][2];
        #pragma unroll
        for (int mi = 0; mi < 4; mi++)
            ldm_x4(af[mi], aAddr[mi] + so + ks * 2);
        #pragma unroll
        for (int p = 0; p < 2; p++) {
            uint32_t r4[4];
            if (BKM) ldm_x4(r4, bAddr[p] + so + ks * 2);
            else     ldm_x4_t(r4, bAddr[p] + so + ks * (BST * 2));
            bf[2 * p + 0][0] = r4[0]; bf[2 * p + 0][1] = r4[1];
            bf[2 * p + 1][0] = r4[2]; bf[2 * p + 1][1] = r4[3];
        }
        #pragma unroll
        for (int mi = 0; mi < 4; mi++)
            #pragma unroll
            for (int ni = 0; ni < 4; ni++)
                mma16816(acc[mi][ni], af[mi], bf[ni]);
    };

    load_stage(0, 0); cp_commit();
    load_stage(1, 1); cp_commit();

    float acc[4][4][4] = {};
    int cs = 0;
    for (int c = 0; c < nk; c++) {
        cp_wait<1>();
        __syncthreads();
        const uint32_t so = (uint32_t)(cs * STG) * 2;
        // kk=0 MMAs first, THEN issue the next-stage cp.async burst,
        // then kk=1 — spreads LSU issue across tensor-busy time.
        do_kk(so, 0, acc);
        if (c + 2 < nk) {
            int ls = cs + 2; if (ls >= 3) ls -= 3;
            load_stage(c + 2, ls);
        }
        cp_commit();
        do_kk(so, 16, acc);
        if (++cs == 3) cs = 0;
    }

    const int g = lane >> 2, t2 = (lane & 3) << 1;
    #pragma unroll
    for (int mi = 0; mi < 4; mi++) {
        #pragma unroll
        for (int half = 0; half < 2; half++) {
            long r = m0 + mi * 16 + g + half * 8;
            #pragma unroll
            for (int ni = 0; ni < 4; ni++) {
                int c = n0 + wn * 32 + ni * 8 + t2;
                float v0 = acc[mi][ni][half * 2 + 0];
                float v1 = acc[mi][ni][half * 2 + 1];
                if (MODE == 1) {
                    v0 = siluf(v0 + bias[c]); v1 = siluf(v1 + bias[c + 1]);
                    *(__half2*)(CH + r * (long)ldch + c) = __floats2half2_rn(v0, v1);
                } else if (MODE == 2) {
                    const __half2 gt = *(const __half2*)(auxH + r * (long)ldaux + c);
                    v0 *= __half2float(gt.x); v1 *= __half2float(gt.y);
                    *(__half2*)(CH + r * (long)ldch + c) = __floats2half2_rn(v0, v1);
                } else if (MODE == 3) {
                    const float2 sres = *(const float2*)(auxF + r * (long)ldaux + c);
                    v0 = (v0 + bias[c]) * (1.f + alpha[c]) + sres.x;
                    v1 = (v1 + bias[c + 1]) * (1.f + alpha[c + 1]) + sres.y;
                    *(float2*)(C + r * (long)ldc + c) = make_float2(v0, v1);
                } else {
                    int d0 = (int)r - c;     d0 = d0 < -64 ? -64 : (d0 > 64 ? 64 : d0);
                    int d1 = (int)r - c - 1; d1 = d1 < -64 ? -64 : (d1 > 64 ? 64 : d1);
                    v0 += bias[c] + rel[d0 + 64];
                    v1 += bias[c + 1] + rel[d1 + 64];
                    *(float2*)(C + r * (long)ldc + c) = make_float2(v0, v1);
                }
            }
        }
    }
}

// ---------------- q/k build + RoPE (reads fp16 h) ----------------------------
__global__ void qk_rope_k(const __half* __restrict__ h, const float* __restrict__ mw,
                          const float* __restrict__ mb, const float* __restrict__ scal,
                          __half* __restrict__ q, __half* __restrict__ k) {
    const int row = blockIdx.x;
    const int t   = threadIdx.x;
    const int pos = row & (LL - 1);
    const __half* base = h + (long)row * GVA_N + 2 * PROJ;
    float b0 = __half2float(base[t]), b1 = __half2float(base[t + 128]);
    float q0 = fmaf(b0, mw[t],       mb[t]);
    float q1 = fmaf(b1, mw[t + 128], mb[t + 128]);
    float k0 = fmaf(b0, mw[256 + t],       mb[256 + t]);
    float k1 = fmaf(b1, mw[256 + t + 128], mb[256 + t + 128]);
    float freq = exp2f(-(float)t * (13.287712379549449f / 128.f));
    float ang = (float)pos * freq;
    float sn, cs; sincosf(ang, &sn, &cs);
    float sc = scal[row];
    q[(long)row * 256 + t]       = __float2half_rn((q0 * cs - q1 * sn) * sc);
    q[(long)row * 256 + t + 128] = __float2half_rn((q1 * cs + q0 * sn) * sc);
    k[(long)row * 256 + t]       = __float2half_rn(k0 * cs - k1 * sn);
    k[(long)row * 256 + t + 128] = __float2half_rn(k1 * cs + k0 * sn);
}

// ---------------- row softmax over 1024 --------------------------------------
__global__ __launch_bounds__(256) void softmax_k(float* __restrict__ S,
                                                 __half* __restrict__ S16,
                                                 int write32) {
    float4* p = (float4*)(S + (long)blockIdx.x * LL);
    __half2* p16 = (__half2*)(S16 + (long)blockIdx.x * LL);
    float4 v = p[threadIdx.x];
    __shared__ float rm[8], rs[8];
    float m = fmaxf(fmaxf(v.x, v.y), fmaxf(v.z, v.w));
    m = warpMax(m);
    if ((threadIdx.x & 31) == 0) rm[threadIdx.x >> 5] = m;
    __syncthreads();
    m = rm[0];
    #pragma unroll
    for (int i = 1; i < 8; i++) m = fmaxf(m, rm[i]);
    v.x = __expf(v.x - m); v.y = __expf(v.y - m);
    v.z = __expf(v.z - m); v.w = __expf(v.w - m);
    float s = v.x + v.y + v.z + v.w;
    s = warpSum(s);
    if ((threadIdx.x & 31) == 0) rs[threadIdx.x >> 5] = s;
    __syncthreads();
    s = 0.f;
    #pragma unroll
    for (int i = 0; i < 8; i++) s += rs[i];
    float inv = 1.f / s;
    v.x *= inv; v.y *= inv; v.z *= inv; v.w *= inv;
    if (write32) p[threadIdx.x] = v;
    p16[threadIdx.x * 2 + 0] = __floats2half2_rn(v.x, v.y);
    p16[threadIdx.x * 2 + 1] = __floats2half2_rn(v.z, v.w);
}

// ---------------- edge = attn[0] + attn[1] (fp32) ----------------------------
__global__ void edge_k(const float* __restrict__ attn, float* __restrict__ e) {
    long i = (long)blockIdx.x * 256 + threadIdx.x;
    float4 a = ((const float4*)attn)[i];
    float4 b = ((const float4*)(attn + (long)LL * LL))[i];
    ((float4*)e)[i] = make_float4(a.x + b.x, a.y + b.y, a.z + b.z, a.w + b.w);
}

// ---------------- launch ------------------------------------------------------
extern "C" void kernel_launch(void* const* d_in, const int* in_sizes, int n_in,
                              void* d_out, int out_size) {
    const float* node      = (const float*)d_in[0];
    const float* qk_scal   = (const float*)d_in[1];
    const float* bias      = (const float*)d_in[2];
    const float* cond      = (const float*)d_in[3];
    const float* w_gva     = (const float*)d_in[4];
    const float* b_gva     = (const float*)d_in[5];
    const float* mhs_w     = (const float*)d_in[6];
    const float* mhs_b     = (const float*)d_in[7];
    const float* relpos    = (const float*)d_in[8];
    const float* w_out     = (const float*)d_in[9];
    const float* b_out     = (const float*)d_in[10];
    const float* w_adaln   = (const float*)d_in[11];
    const float* b_adaln   = (const float*)d_in[12];
    float* out = (float*)d_out;

    float *sc, *part, *gba, *attn, *nodeb;
    __half *x16, *h16, *q16, *k16, *attn16, *av16, *wg16, *wo16;
    cudaGetSymbolAddress((void**)&sc,     d_sc);
    cudaGetSymbolAddress((void**)&part,   d_part);
    cudaGetSymbolAddress((void**)&gba,    d_gba);
    cudaGetSymbolAddress((void**)&x16,    d_x16);
    cudaGetSymbolAddress((void**)&h16,    d_h16);
    cudaGetSymbolAddress((void**)&q16,    d_q16);
    cudaGetSymbolAddress((void**)&k16,    d_k16);
    cudaGetSymbolAddress((void**)&attn,   d_attn);
    cudaGetSymbolAddress((void**)&attn16, d_attn16);
    cudaGetSymbolAddress((void**)&av16,   d_av16);
    cudaGetSymbolAddress((void**)&nodeb,  d_node);
    cudaGetSymbolAddress((void**)&wg16,   d_wgva16);
    cudaGetSymbolAddress((void**)&wo16,   d_wout16);

    static cudaStream_t s2 = nullptr;
    static cudaEvent_t evFork = nullptr, evJoin0 = nullptr, evJoin = nullptr;
    if (s2 == nullptr) {
        cudaStreamCreateWithFlags(&s2, cudaStreamNonBlocking);
        cudaEventCreateWithFlags(&evFork,  cudaEventDisableTiming);
        cudaEventCreateWithFlags(&evJoin0, cudaEventDisableTiming);
        cudaEventCreateWithFlags(&evJoin,  cudaEventDisableTiming);
    }

    const int SMW64 = 3 * (64 * AST + 32 * 136) * 2;   // 41472
    const int SMK64 = 3 * (64 * AST + 128 * 40) * 2;   // 46080
    cudaFuncSetAttribute(hgemm<1, false>, cudaFuncAttributeMaxDynamicSharedMemorySize, SMW64);
    cudaFuncSetAttribute(hgemm<2, false>, cudaFuncAttributeMaxDynamicSharedMemorySize, SMW64);
    cudaFuncSetAttribute(hgemm<3, false>, cudaFuncAttributeMaxDynamicSharedMemorySize, SMW64);
    cudaFuncSetAttribute(hgemm<4, true>,  cudaFuncAttributeMaxDynamicSharedMemorySize, SMK64);

    const long WGL = (long)NODE * GVA_N;               // wgva elems per layer

    // fork first: layer-0 GVA weights convert on s2, overlapping the adaLN chain
    cudaEventRecord(evFork, 0);
    cudaStreamWaitEvent(s2, evFork, 0);
    f2h_k<<<(int)(WGL / 1024), 256, 0, s2>>>(w_gva, wg16);
    cudaEventRecord(evJoin0, s2);
    // bulk conversions continue on s2, overlapped with layer-0 compute
    f2h_k<<<(int)(3 * WGL / 1024), 256, 0, s2>>>(w_gva + WGL, wg16 + WGL);
    f2h_k<<<(int)((long)NL * PROJ * NODE / 1024), 256, 0, s2>>>(w_out, wo16);
    cudaEventRecord(evJoin, s2);

    // main stream: adaLN chain (independent of weight conversion)
    cudaMemcpyAsync(nodeb, node, (size_t)ROWS * NODE * sizeof(float),
                    cudaMemcpyDeviceToDevice);
    silu_vec_k<<<(BB * NODE + 255) / 256, 256>>>(cond, sc, BB * NODE);
    adaln_part_k<<<dim3(ADALN_N / 256, BB * KS, NL), 256>>>(sc, w_adaln, part);
    adaln_reduce_k<<<(NL * BB * ADALN_N) / 256, 256>>>(part, b_adaln, gba);

    bool joined = false;
    for (int l = 0; l < NL; l++) {
        const float* gba_l = gba + (long)l * BB * ADALN_N;

        ln_mod_k<<<ROWS, 256>>>(nodeb, gba_l, x16);

        if (l == 0) cudaStreamWaitEvent(0, evJoin0, 0);   // wg16 L0 ready

        // h16 = silu(x @ w_gva + b_gva)
        hgemm<1, false><<<dim3(GVA_N / 128, ROWS / 64, 1), 128, SMW64>>>(
            NODE,
            x16, NODE, 0L,
            wg16 + (long)l * WGL, GVA_N, 0L,
            nullptr, 0, 0L,
            h16, GVA_N, 0L,
            b_gva + l * GVA_N,
            nullptr, 0, 0L, nullptr, nullptr, 0, nullptr);

        qk_rope_k<<<ROWS, 128>>>(h16, mhs_w + l * 2 * ATTND, mhs_b + l * 2 * ATTND,
                                 qk_scal, q16, k16);

        // logits = q @ k^T + bias + rel
        hgemm<4, true><<<dim3(LL / 128, LL / 64, BB), 128, SMK64>>>(
            ATTND,
            q16, ATTND, (long)LL * ATTND,
            k16, ATTND, (long)LL * ATTND,
            attn, LL, (long)LL * LL,
            nullptr, 0, 0L,
            bias,
            nullptr, 0, 0L, nullptr, nullptr, 0,
            relpos + l * NREL);

        softmax_k<<<ROWS, 256>>>(attn, attn16, (l == NL - 1) ? 1 : 0);

        if (l == NL - 1)
            edge_k<<<(LL * LL / 4) / 256, 256>>>(attn, out + (long)ROWS * NODE);

        // av16 = (attn @ values) * gates
        hgemm<2, false><<<dim3(PROJ / 128, LL / 64, BB), 128, SMW64>>>(
            LL,
            attn16, LL, (long)LL * LL,
            h16 + PROJ, GVA_N, (long)LL * GVA_N,
            nullptr, 0, 0L,
            av16, PROJ, (long)LL * PROJ,
            nullptr,
            h16, GVA_N, (long)LL * GVA_N,
            nullptr, nullptr, 0, nullptr);

        if (!joined) {
            cudaStreamWaitEvent(0, evJoin, 0);            // wo16 + wg16 L1-3 ready
            joined = true;
        }

        // node = (av @ w_out + b_out)*(1+alpha) + shortcut
        float* Cdst = (l == NL - 1) ? out : nodeb;
        hgemm<3, false><<<dim3(NODE / 128, LL / 64, BB), 128, SMW64>>>(
            PROJ,
            av16, PROJ, (long)LL * PROJ,
            wo16 + (long)l * PROJ * NODE, NODE, 0L,
            Cdst, NODE, (long)LL * NODE,
            nullptr, 0, 0L,
            b_out + l * NODE,
            nullptr, NODE, (long)LL * NODE,
            nodeb,
            gba_l + 2 * NODE, ADALN_N, nullptr);
    }
    (void)in_sizes; (void)n_in; (void)out_size;
}

// round 15
// speedup vs baseline: 1.0321x; 1.0109x over previous
#include <cuda_runtime.h>
#include <cuda_fp16.h>
#include <cstdint>
#include <math.h>

#define NODE   1280
#define PROJ   2560
#define ATTND  256
#define NREL   129
#define NL     4
#define BB     2
#define LL     1024
#define GVA_N  (2*PROJ + ATTND)   // 5376
#define ADALN_N (3*NODE)          // 3840
#define ROWS   (BB*LL)            // 2048
#define KS     10                 // adaLN split-K factor

// ---------------- scratch (device globals; no allocation allowed) ----------
__device__ float  d_sc    [BB*NODE];
__device__ float  d_part  [NL*BB*KS*ADALN_N];
__device__ float  d_gba   [NL*BB*ADALN_N];
__device__ __half d_x16   [ROWS*NODE];
__device__ __half d_h16   [ROWS*GVA_N];
__device__ __half d_q16   [ROWS*ATTND];
__device__ __half d_k16   [ROWS*ATTND];
__device__ __half d_attn16[(long)BB*LL*LL];
__device__ __half d_av16  [ROWS*PROJ];
__device__ float  d_node  [ROWS*NODE];
__device__ __half d_wgva16[(long)NL*NODE*GVA_N];
__device__ __half d_wout16[(long)NL*PROJ*NODE];

// ---------------- helpers ---------------------------------------------------
__device__ __forceinline__ float siluf(float x) { return x / (1.f + __expf(-x)); }
__device__ __forceinline__ float warpMax(float v) {
    #pragma unroll
    for (int o = 16; o > 0; o >>= 1) v = fmaxf(v, __shfl_xor_sync(0xffffffffu, v, o));
    return v;
}
__device__ __forceinline__ float warpSum(float v) {
    #pragma unroll
    for (int o = 16; o > 0; o >>= 1) v += __shfl_xor_sync(0xffffffffu, v, o);
    return v;
}
__device__ __forceinline__ uint32_t smem_u32(const void* p) {
    uint32_t a;
    asm("{ .reg .u64 t; cvta.to.shared.u64 t, %1; cvt.u32.u64 %0, t; }"
        : "=r"(a) : "l"(p));
    return a;
}
__device__ __forceinline__ void cp16(uint32_t dst, const void* src) {
    asm volatile("cp.async.cg.shared.global [%0], [%1], 16;" :: "r"(dst), "l"(src));
}
__device__ __forceinline__ void cp_commit() {
    asm volatile("cp.async.commit_group;" ::: "memory");
}
template <int N>
__device__ __forceinline__ void cp_wait() {
    asm volatile("cp.async.wait_group %0;" :: "n"(N) : "memory");
}
__device__ __forceinline__ void ldm_x4(uint32_t* r, uint32_t a) {
    asm volatile("ldmatrix.sync.aligned.m8n8.x4.shared.b16 {%0,%1,%2,%3}, [%4];"
                 : "=r"(r[0]), "=r"(r[1]), "=r"(r[2]), "=r"(r[3]) : "r"(a));
}
__device__ __forceinline__ void ldm_x4_t(uint32_t* r, uint32_t a) {
    asm volatile("ldmatrix.sync.aligned.m8n8.x4.trans.shared.b16 {%0,%1,%2,%3}, [%4];"
                 : "=r"(r[0]), "=r"(r[1]), "=r"(r[2]), "=r"(r[3]) : "r"(a));
}
__device__ __forceinline__ void mma16816(float* c, const uint32_t* a, const uint32_t* b) {
    asm volatile(
        "mma.sync.aligned.m16n8k16.row.col.f32.f16.f16.f32 "
        "{%0,%1,%2,%3}, {%4,%5,%6,%7}, {%8,%9}, {%0,%1,%2,%3};"
        : "+f"(c[0]), "+f"(c[1]), "+f"(c[2]), "+f"(c[3])
        : "r"(a[0]), "r"(a[1]), "r"(a[2]), "r"(a[3]), "r"(b[0]), "r"(b[1]));
}

// ---------------- small kernels ---------------------------------------------
__global__ void silu_vec_k(const float* __restrict__ c, float* __restrict__ sc, int n) {
    int i = blockIdx.x * 256 + threadIdx.x;
    if (i < n) sc[i] = siluf(c[i]);
}

__global__ void f2h_k(const float* __restrict__ in, __half* __restrict__ out) {
    long i = (long)blockIdx.x * 256 + threadIdx.x;
    float4 v = ((const float4*)in)[i];
    ((__half2*)out)[2 * i]     = __floats2half2_rn(v.x, v.y);
    ((__half2*)out)[2 * i + 1] = __floats2half2_rn(v.z, v.w);
}

__global__ void adaln_part_k(const float* __restrict__ sc, const float* __restrict__ w,
                             float* __restrict__ part) {
    const int l = blockIdx.z;
    const int b = blockIdx.y / KS, ks = blockIdx.y % KS;
    const int col = blockIdx.x * 256 + threadIdx.x;
    const int KC = NODE / KS;
    const float* s  = sc + b * NODE + ks * KC;
    const float* wp = w + (long)l * NODE * ADALN_N + (long)ks * KC * ADALN_N + col;
    float a0 = 0.f, a1 = 0.f, a2 = 0.f, a3 = 0.f;
    #pragma unroll 4
    for (int k = 0; k < KC; k += 4) {
        a0 = fmaf(s[k],     wp[(long)k * ADALN_N],       a0);
        a1 = fmaf(s[k + 1], wp[(long)(k + 1) * ADALN_N], a1);
        a2 = fmaf(s[k + 2], wp[(long)(k + 2) * ADALN_N], a2);
        a3 = fmaf(s[k + 3], wp[(long)(k + 3) * ADALN_N], a3);
    }
    part[((((long)l * BB) + b) * KS + ks) * ADALN_N + col] = (a0 + a1) + (a2 + a3);
}
__global__ void adaln_reduce_k(const float* __restrict__ part,
                               const float* __restrict__ bvec, float* __restrict__ gba) {
    long idx = (long)blockIdx.x * 256 + threadIdx.x;
    int l = (int)(idx / (BB * ADALN_N));
    int rem = (int)(idx % (BB * ADALN_N));
    int b = rem / ADALN_N, col = rem % ADALN_N;
    const float* p = part + (((long)l * BB + b) * KS) * ADALN_N + col;
    float acc = bvec[l * ADALN_N + col];
    #pragma unroll
    for (int i = 0; i < KS; i++) acc += p[(long)i * ADALN_N];
    gba[idx] = acc;
}

// LayerNorm + modulate -> fp16 x
__global__ __launch_bounds__(256) void ln_mod_k(const float* __restrict__ node,
                                                const float* __restrict__ gba,
                                                __half* __restrict__ x16) {
    const int row = blockIdx.x;
    const int b   = row >> 10;
    const float* p = node + (long)row * NODE;
    float vals[5];
    float s = 0.f, sq = 0.f;
    #pragma unroll
    for (int i = 0; i < 5; i++) {
        float v = p[threadIdx.x + i * 256];
        vals[i] = v; s += v; sq += v * v;
    }
    __shared__ float rs[8], rq[8];
    s = warpSum(s); sq = warpSum(sq);
    if ((threadIdx.x & 31) == 0) { rs[threadIdx.x >> 5] = s; rq[threadIdx.x >> 5] = sq; }
    __syncthreads();
    float ts = 0.f, tq = 0.f;
    #pragma unroll
    for (int i = 0; i < 8; i++) { ts += rs[i]; tq += rq[i]; }
    const float mean = ts * (1.f / NODE);
    const float var  = tq * (1.f / NODE) - mean * mean;
    const float rstd = rsqrtf(var + 1e-5f);
    const float* g = gba + (long)b * ADALN_N;
    __half* xo = x16 + (long)row * NODE;
    #pragma unroll
    for (int i = 0; i < 5; i++) {
        int c = threadIdx.x + i * 256;
        float v = (vals[i] - mean) * rstd;
        xo[c] = __float2half_rn(v * (1.f + g[c]) + g[NODE + c]);
    }
}

// ============================================================================
// fp16 mma.sync GEMM, reordered mainloop (kk0 MMAs -> cp.async -> kk1 MMAs).
//  MT=128: 256 threads, 8 warps (64x32 warp tile), occ 2  (GVA)
//  MT=64 : 128 threads, 4 warps (64x32 warp tile), occ 5 (4 if BKM)
// MODE 1: CH = silu(acc + bias[n])                 (fp16 out)
// MODE 2: CH = acc * auxH[m,n]                     (fp16 out)
// MODE 3: C  = (acc + bias[n])*(1+alpha[n]) + auxF (fp32 out)
// MODE 4: CH = acc + bias[z,n] + rel[clamp(m-n)]   (fp16 logits out)
// ============================================================================
#define AST 40              // A row stride (halfs)

template <int MODE, bool BKM, int MT>
__global__ __launch_bounds__((MT == 128 ? 256 : 128),
                             (MT == 128 ? 2 : (BKM ? 4 : 5))) void hgemm(
    int K,
    const __half* __restrict__ A, int lda, long sA,
    const __half* __restrict__ B, int ldb, long sB,
    float* __restrict__ C, int ldc, long sC,
    __half* __restrict__ CH, int ldch, long sCh,
    const float* __restrict__ bias,
    const __half* __restrict__ auxH, int ldaux, long sAux,
    const float* __restrict__ auxF,
    const float* __restrict__ alphaP, int sAlpha,
    const float* __restrict__ rel) {
    constexpr int THREADS = (MT == 128) ? 256 : 128;
    constexpr int BST = BKM ? 40 : 136;
    constexpr int ASZ2 = MT * AST;
    constexpr int BSZ = BKM ? 128 * 40 : 32 * 136;
    constexpr int STG = ASZ2 + BSZ;
    constexpr int AITER = (MT * 4) / THREADS;
    constexpr int BITER = 512 / THREADS;

    extern __shared__ __half sh[];
    const int z = blockIdx.z;
    A += z * sA; B += z * sB;
    if (MODE == 3) C += z * sC;
    if (MODE == 1 || MODE == 2 || MODE == 4) CH += z * sCh;
    if (MODE == 2) auxH += z * sAux;
    if (MODE == 3) auxF += z * sAux;
    if (MODE == 4) bias += (long)z * LL;
    const float* alpha = (MODE == 3) ? (alphaP + (long)z * sAlpha) : nullptr;

    const int tid = threadIdx.x, wid = tid >> 5, lane = tid & 31;
    const int wm = (MT == 128) ? (wid & 1) : 0;
    const int wn = (MT == 128) ? (wid >> 1) : wid;
    const int m0 = blockIdx.y * MT, n0 = blockIdx.x * 128;
    const uint32_t smb = smem_u32(sh);
    const int nk = K >> 5;

    uint32_t aAddr[4], bAddr[2];
    #pragma unroll
    for (int mi = 0; mi < 4; mi++) {
        int off = (wm * 64 + mi * 16 + (lane & 15)) * AST + ((lane >> 4) << 3);
        aAddr[mi] = smb + off * 2;
    }
    #pragma unroll
    for (int p = 0; p < 2; p++) {
        int off;
        if (BKM)
            off = (wn * 32 + p * 16 + (lane & 7) + ((lane >> 4) << 3)) * BST
                  + (((lane >> 3) & 1) << 3);
        else
            off = (lane & 15) * BST + wn * 32 + p * 16 + ((lane >> 4) << 3);
        bAddr[p] = smb + (ASZ2 + off) * 2;
    }

    auto load_stage = [&](int c, int slot) {
        const uint32_t ab = smb + (uint32_t)(slot * STG) * 2;
        const uint32_t bb = ab + ASZ2 * 2;
        #pragma unroll
        for (int i = 0; i < AITER; i++) {
            int v = tid + i * THREADS;
            int r = v >> 2, ch = v & 3;
            cp16(ab + (uint32_t)(r * AST + ch * 8) * 2,
                 A + (long)(m0 + r) * lda + c * 32 + ch * 8);
        }
        if (BKM) {
            #pragma unroll
            for (int i = 0; i < BITER; i++) {
                int v = tid + i * THREADS;
                int r = v >> 2, ch = v & 3;
                cp16(bb + (uint32_t)(r * BST + ch * 8) * 2,
                     B + (long)(n0 + r) * ldb + c * 32 + ch * 8);
            }
        } else {
            #pragma unroll
            for (int i = 0; i < BITER; i++) {
                int v = tid + i * THREADS;
                int r = v >> 4, ch = v & 15;
                cp16(bb + (uint32_t)(r * BST + ch * 8) * 2,
                     B + (long)(c * 32 + r) * ldb + n0 + ch * 8);
            }
        }
    };

    auto do_kk = [&](uint32_t so, int ks, float (*acc)[4][4]) {
        uint32_t af[4][4], bf[4][2];
        #pragma unroll
        for (int mi = 0; mi < 4; mi++)
            ldm_x4(af[mi], aAddr[mi] + so + ks * 2);
        #pragma unroll
        for (int p = 0; p < 2; p++) {
            uint32_t r4[4];
            if (BKM) ldm_x4(r4, bAddr[p] + so + ks * 2);
            else     ldm_x4_t(r4, bAddr[p] + so + ks * (BST * 2));
            bf[2 * p + 0][0] = r4[0]; bf[2 * p + 0][1] = r4[1];
            bf[2 * p + 1][0] = r4[2]; bf[2 * p + 1][1] = r4[3];
        }
        #pragma unroll
        for (int mi = 0; mi < 4; mi++)
            #pragma unroll
            for (int ni = 0; ni < 4; ni++)
                mma16816(acc[mi][ni], af[mi], bf[ni]);
    };

    load_stage(0, 0); cp_commit();
    load_stage(1, 1); cp_commit();

    float acc[4][4][4] = {};
    int cs = 0;
    for (int c = 0; c < nk; c++) {
        cp_wait<1>();
        __syncthreads();
        const uint32_t so = (uint32_t)(cs * STG) * 2;
        do_kk(so, 0, acc);
        if (c + 2 < nk) {
            int ls = cs + 2; if (ls >= 3) ls -= 3;
            load_stage(c + 2, ls);
        }
        cp_commit();
        do_kk(so, 16, acc);
        if (++cs == 3) cs = 0;
    }

    const int g = lane >> 2, t2 = (lane & 3) << 1;
    #pragma unroll
    for (int mi = 0; mi < 4; mi++) {
        #pragma unroll
        for (int half = 0; half < 2; half++) {
            long r = m0 + wm * 64 + mi * 16 + g + half * 8;
            #pragma unroll
            for (int ni = 0; ni < 4; ni++) {
                int c = n0 + wn * 32 + ni * 8 + t2;
                float v0 = acc[mi][ni][half * 2 + 0];
                float v1 = acc[mi][ni][half * 2 + 1];
                if (MODE == 1) {
                    v0 = siluf(v0 + bias[c]); v1 = siluf(v1 + bias[c + 1]);
                    *(__half2*)(CH + r * (long)ldch + c) = __floats2half2_rn(v0, v1);
                } else if (MODE == 2) {
                    const __half2 gt = *(const __half2*)(auxH + r * (long)ldaux + c);
                    v0 *= __half2float(gt.x); v1 *= __half2float(gt.y);
                    *(__half2*)(CH + r * (long)ldch + c) = __floats2half2_rn(v0, v1);
                } else if (MODE == 3) {
                    const float2 sres = *(const float2*)(auxF + r * (long)ldaux + c);
                    v0 = (v0 + bias[c]) * (1.f + alpha[c]) + sres.x;
                    v1 = (v1 + bias[c + 1]) * (1.f + alpha[c + 1]) + sres.y;
                    *(float2*)(C + r * (long)ldc + c) = make_float2(v0, v1);
                } else {
                    int d0 = (int)r - c;     d0 = d0 < -64 ? -64 : (d0 > 64 ? 64 : d0);
                    int d1 = (int)r - c - 1; d1 = d1 < -64 ? -64 : (d1 > 64 ? 64 : d1);
                    v0 += bias[c] + rel[d0 + 64];
                    v1 += bias[c + 1] + rel[d1 + 64];
                    *(__half2*)(CH + r * (long)ldch + c) = __floats2half2_rn(v0, v1);
                }
            }
        }
    }
}

// ---------------- q/k build + RoPE (reads fp16 h) ----------------------------
__global__ void qk_rope_k(const __half* __restrict__ h, const float* __restrict__ mw,
                          const float* __restrict__ mb, const float* __restrict__ scal,
                          __half* __restrict__ q, __half* __restrict__ k) {
    const int row = blockIdx.x;
    const int t   = threadIdx.x;
    const int pos = row & (LL - 1);
    const __half* base = h + (long)row * GVA_N + 2 * PROJ;
    float b0 = __half2float(base[t]), b1 = __half2float(base[t + 128]);
    float q0 = fmaf(b0, mw[t],       mb[t]);
    float q1 = fmaf(b1, mw[t + 128], mb[t + 128]);
    float k0 = fmaf(b0, mw[256 + t],       mb[256 + t]);
    float k1 = fmaf(b1, mw[256 + t + 128], mb[256 + t + 128]);
    float freq = exp2f(-(float)t * (13.287712379549449f / 128.f));
    float ang = (float)pos * freq;
    float sn, cs; sincosf(ang, &sn, &cs);
    float sc = scal[row];
    q[(long)row * 256 + t]       = __float2half_rn((q0 * cs - q1 * sn) * sc);
    q[(long)row * 256 + t + 128] = __float2half_rn((q1 * cs + q0 * sn) * sc);
    k[(long)row * 256 + t]       = __float2half_rn(k0 * cs - k1 * sn);
    k[(long)row * 256 + t + 128] = __float2half_rn(k1 * cs + k0 * sn);
}

// ---------------- row softmax over 1024, in-place fp16 -----------------------
__global__ __launch_bounds__(256) void softmax_k(__half* __restrict__ S16) {
    __half2* p = (__half2*)(S16 + (long)blockIdx.x * LL);
    __half2 h0 = p[threadIdx.x * 2], h1 = p[threadIdx.x * 2 + 1];
    float v0 = __half2float(h0.x), v1 = __half2float(h0.y);
    float v2 = __half2float(h1.x), v3 = __half2float(h1.y);
    __shared__ float rm[8], rs[8];
    float m = fmaxf(fmaxf(v0, v1), fmaxf(v2, v3));
    m = warpMax(m);
    if ((threadIdx.x & 31) == 0) rm[threadIdx.x >> 5] = m;
    __syncthreads();
    m = rm[0];
    #pragma unroll
    for (int i = 1; i < 8; i++) m = fmaxf(m, rm[i]);
    v0 = __expf(v0 - m); v1 = __expf(v1 - m);
    v2 = __expf(v2 - m); v3 = __expf(v3 - m);
    float s = v0 + v1 + v2 + v3;
    s = warpSum(s);
    if ((threadIdx.x & 31) == 0) rs[threadIdx.x >> 5] = s;
    __syncthreads();
    s = 0.f;
    #pragma unroll
    for (int i = 0; i < 8; i++) s += rs[i];
    float inv = 1.f / s;
    p[threadIdx.x * 2]     = __floats2half2_rn(v0 * inv, v1 * inv);
    p[threadIdx.x * 2 + 1] = __floats2half2_rn(v2 * inv, v3 * inv);
}

// ---------------- edge = attn16[0] + attn16[1] -> fp32 -----------------------
__global__ void edge_k(const __half* __restrict__ attn, float* __restrict__ e) {
    long i = (long)blockIdx.x * 256 + threadIdx.x;     // over LL*LL/2 half2s
    __half2 a = ((const __half2*)attn)[i];
    __half2 b = ((const __half2*)(attn + (long)LL * LL))[i];
    ((float2*)e)[i] = make_float2(__half2float(a.x) + __half2float(b.x),
                                  __half2float(a.y) + __half2float(b.y));
}

// ---------------- launch ------------------------------------------------------
extern "C" void kernel_launch(void* const* d_in, const int* in_sizes, int n_in,
                              void* d_out, int out_size) {
    const float* node      = (const float*)d_in[0];
    const float* qk_scal   = (const float*)d_in[1];
    const float* bias      = (const float*)d_in[2];
    const float* cond      = (const float*)d_in[3];
    const float* w_gva     = (const float*)d_in[4];
    const float* b_gva     = (const float*)d_in[5];
    const float* mhs_w     = (const float*)d_in[6];
    const float* mhs_b     = (const float*)d_in[7];
    const float* relpos    = (const float*)d_in[8];
    const float* w_out     = (const float*)d_in[9];
    const float* b_out     = (const float*)d_in[10];
    const float* w_adaln   = (const float*)d_in[11];
    const float* b_adaln   = (const float*)d_in[12];
    float* out = (float*)d_out;

    float *sc, *part, *gba, *nodeb;
    __half *x16, *h16, *q16, *k16, *attn16, *av16, *wg16, *wo16;
    cudaGetSymbolAddress((void**)&sc,     d_sc);
    cudaGetSymbolAddress((void**)&part,   d_part);
    cudaGetSymbolAddress((void**)&gba,    d_gba);
    cudaGetSymbolAddress((void**)&x16,    d_x16);
    cudaGetSymbolAddress((void**)&h16,    d_h16);
    cudaGetSymbolAddress((void**)&q16,    d_q16);
    cudaGetSymbolAddress((void**)&k16,    d_k16);
    cudaGetSymbolAddress((void**)&attn16, d_attn16);
    cudaGetSymbolAddress((void**)&av16,   d_av16);
    cudaGetSymbolAddress((void**)&nodeb,  d_node);
    cudaGetSymbolAddress((void**)&wg16,   d_wgva16);
    cudaGetSymbolAddress((void**)&wo16,   d_wout16);

    static cudaStream_t s2 = nullptr;
    static cudaEvent_t evFork = nullptr, evJoin0 = nullptr, evJoin = nullptr;
    if (s2 == nullptr) {
        cudaStreamCreateWithFlags(&s2, cudaStreamNonBlocking);
        cudaEventCreateWithFlags(&evFork,  cudaEventDisableTiming);
        cudaEventCreateWithFlags(&evJoin0, cudaEventDisableTiming);
        cudaEventCreateWithFlags(&evJoin,  cudaEventDisableTiming);
    }

    const int SMW128 = 3 * (128 * AST + 32 * 136) * 2;  // 56832 (GVA)
    const int SMW64  = 3 * (64 * AST + 32 * 136) * 2;   // 41472 (AV, out-proj)
    const int SMK64  = 3 * (64 * AST + 128 * 40) * 2;   // 46080 (logits)
    cudaFuncSetAttribute(hgemm<1, false, 128>, cudaFuncAttributeMaxDynamicSharedMemorySize, SMW128);
    cudaFuncSetAttribute(hgemm<2, false, 64>,  cudaFuncAttributeMaxDynamicSharedMemorySize, SMW64);
    cudaFuncSetAttribute(hgemm<3, false, 64>,  cudaFuncAttributeMaxDynamicSharedMemorySize, SMW64);
    cudaFuncSetAttribute(hgemm<4, true, 64>,   cudaFuncAttributeMaxDynamicSharedMemorySize, SMK64);

    const long WGL = (long)NODE * GVA_N;

    // fork: weight conversions on s2 overlap the adaLN chain + layer-0 compute
    cudaEventRecord(evFork, 0);
    cudaStreamWaitEvent(s2, evFork, 0);
    f2h_k<<<(int)(WGL / 1024), 256, 0, s2>>>(w_gva, wg16);
    cudaEventRecord(evJoin0, s2);
    f2h_k<<<(int)(3 * WGL / 1024), 256, 0, s2>>>(w_gva + WGL, wg16 + WGL);
    f2h_k<<<(int)((long)NL * PROJ * NODE / 1024), 256, 0, s2>>>(w_out, wo16);
    cudaEventRecord(evJoin, s2);

    cudaMemcpyAsync(nodeb, node, (size_t)ROWS * NODE * sizeof(float),
                    cudaMemcpyDeviceToDevice);
    silu_vec_k<<<(BB * NODE + 255) / 256, 256>>>(cond, sc, BB * NODE);
    adaln_part_k<<<dim3(ADALN_N / 256, BB * KS, NL), 256>>>(sc, w_adaln, part);
    adaln_reduce_k<<<(NL * BB * ADALN_N) / 256, 256>>>(part, b_adaln, gba);

    bool joined = false;
    for (int l = 0; l < NL; l++) {
        const float* gba_l = gba + (long)l * BB * ADALN_N;

        ln_mod_k<<<ROWS, 256>>>(nodeb, gba_l, x16);

        if (l == 0) cudaStreamWaitEvent(0, evJoin0, 0);

        // h16 = silu(x @ w_gva + b_gva), MT=128 / 256 threads
        hgemm<1, false, 128><<<dim3(GVA_N / 128, ROWS / 128, 1), 256, SMW128>>>(
            NODE,
            x16, NODE, 0L,
            wg16 + (long)l * WGL, GVA_N, 0L,
            nullptr, 0, 0L,
            h16, GVA_N, 0L,
            b_gva + l * GVA_N,
            nullptr, 0, 0L, nullptr, nullptr, 0, nullptr);

        qk_rope_k<<<ROWS, 128>>>(h16, mhs_w + l * 2 * ATTND, mhs_b + l * 2 * ATTND,
                                 qk_scal, q16, k16);

        // logits = q @ k^T + bias + rel -> fp16
        hgemm<4, true, 64><<<dim3(LL / 128, LL / 64, BB), 128, SMK64>>>(
            ATTND,
            q16, ATTND, (long)LL * ATTND,
            k16, ATTND, (long)LL * ATTND,
            nullptr, 0, 0L,
            attn16, LL, (long)LL * LL,
            bias,
            nullptr, 0, 0L, nullptr, nullptr, 0,
            relpos + l * NREL);

        softmax_k<<<ROWS, 256>>>(attn16);

        if (l == NL - 1)
            edge_k<<<(LL * LL / 2) / 256, 256>>>(attn16, out + (long)ROWS * NODE);

        // av16 = (attn @ values) * gates
        hgemm<2, false, 64><<<dim3(PROJ / 128, LL / 64, BB), 128, SMW64>>>(
            LL,
            attn16, LL, (long)LL * LL,
            h16 + PROJ, GVA_N, (long)LL * GVA_N,
            nullptr, 0, 0L,
            av16, PROJ, (long)LL * PROJ,
            nullptr,
            h16, GVA_N, (long)LL * GVA_N,
            nullptr, nullptr, 0, nullptr);

        if (!joined) {
            cudaStreamWaitEvent(0, evJoin, 0);
            joined = true;
        }

        // node = (av @ w_out + b_out)*(1+alpha) + shortcut
        float* Cdst = (l == NL - 1) ? out : nodeb;
        hgemm<3, false, 64><<<dim3(NODE / 128, LL / 64, BB), 128, SMW64>>>(
            PROJ,
            av16, PROJ, (long)LL * PROJ,
            wo16 + (long)l * PROJ * NODE, NODE, 0L,
            Cdst, NODE, (long)LL * NODE,
            nullptr, 0, 0L,
            b_out + l * NODE,
            nullptr, NODE, (long)LL * NODE,
            nodeb,
            gba_l + 2 * NODE, ADALN_N, nullptr);
    }
    (void)in_sizes; (void)n_in; (void)out_size;
}